// round 13
// baseline (speedup 1.0000x reference)
#include <cuda_runtime.h>
#include <cuda_fp16.h>
#include <cstdint>

#define B_   4
#define C_   256
#define H_   256
#define W_   256
#define HW_  65536

// Scratch (device globals; uint4 for 16B alignment)
__device__ uint4 d_qkvh_[(long long)B_ * 768 * HW_ / 8];
__device__ uint4 d_attnh_[(long long)B_ * C_ * HW_ / 8];
__device__ uint4 d_vgh_[(long long)B_ * C_ * HW_ / 8];
__device__ uint4 d_preh_[(long long)B_ * C_ * HW_ / 8];
__device__ uint4 d_wtq_[768 * 256 / 8];
__device__ uint4 d_wtg_[256 * 256 / 8];
__device__ uint4 d_wtp_[256 * 256 / 8];

// ---------------------------------------------------------------------------
__device__ __forceinline__ uint32_t smem_u32(const void* p) {
    uint32_t a;
    asm("{ .reg .u64 t; cvta.to.shared.u64 t, %1; cvt.u32.u64 %0, t; }" : "=r"(a) : "l"(p));
    return a;
}
__device__ __forceinline__ void cp16(uint32_t s, const void* g) {
    asm volatile("cp.async.cg.shared.global [%0], [%1], 16;" :: "r"(s), "l"(g));
}
#define CP_COMMIT() asm volatile("cp.async.commit_group;" ::: "memory")
#define CP_WAIT(N)  asm volatile("cp.async.wait_group %0;" :: "n"(N) : "memory")

__device__ __forceinline__ void ldsm4t(uint32_t* r, uint32_t a) {
    asm volatile("ldmatrix.sync.aligned.m8n8.x4.trans.shared.b16 {%0,%1,%2,%3}, [%4];"
                 : "=r"(r[0]), "=r"(r[1]), "=r"(r[2]), "=r"(r[3]) : "r"(a));
}
__device__ __forceinline__ void mma16816(float* d, const uint32_t* a, uint32_t b0, uint32_t b1) {
    asm volatile(
        "mma.sync.aligned.m16n8k16.row.col.f32.f16.f16.f32 "
        "{%0,%1,%2,%3}, {%4,%5,%6,%7}, {%8,%9}, {%0,%1,%2,%3};"
        : "+f"(d[0]), "+f"(d[1]), "+f"(d[2]), "+f"(d[3])
        : "r"(a[0]), "r"(a[1]), "r"(a[2]), "r"(a[3]), "r"(b0), "r"(b1));
}
__device__ __forceinline__ float4 ld4h(const __half* p) {
    uint2 u = *(const uint2*)p;
    __half2 a = *(__half2*)&u.x;
    __half2 b = *(__half2*)&u.y;
    float2 fa = __half22float2(a), fb = __half22float2(b);
    return make_float4(fa.x, fa.y, fb.x, fb.y);
}
__device__ __forceinline__ void st4h(__half* p, float x, float y, float z, float w) {
    uint2 u;
    *(__half2*)&u.x = __floats2half2_rn(x, y);
    *(__half2*)&u.y = __floats2half2_rn(z, w);
    *(uint2*)p = u;
}
__device__ __forceinline__ uint32_t packh2(float a, float b) {
    __half2 h = __floats2half2_rn(a, b);
    return *(uint32_t*)&h;
}

// ---------------------------------------------------------------------------
// Pre-pass: weight transposes only (x conversion fused into qkv GEMM)
// ---------------------------------------------------------------------------
__global__ void __launch_bounds__(256) prepass_kernel(
    const float* __restrict__ qkv_w, const float* __restrict__ gaze_pw,
    const float* __restrict__ proj_w,
    __half* __restrict__ wtq, __half* __restrict__ wtg, __half* __restrict__ wtp)
{
    int i = blockIdx.x * 256 + threadIdx.x;
    if (i < 196608) {
        int k = i / 768, m = i - k * 768;
        wtq[i] = __float2half_rn(qkv_w[m * 256 + k]);
    } else if (i < 262144) {
        int j = i - 196608;
        int k = j >> 8, m = j & 255;
        wtg[j] = __float2half_rn(gaze_pw[m * 256 + k]);
    } else {
        int j = i - 262144;
        int k = j >> 8, m = j & 255;
        wtp[j] = __float2half_rn(proj_w[m * 256 + k]);
    }
}

// ---------------------------------------------------------------------------
// qkv GEMM: X staged DIRECTLY from fp32 global (reg convert -> STS),
// W via 4-stage cp.async ring. CTA 128m x 128p, 2 CTA/SM.
// smem: W ring 4 x 8KB (0..32767), X double buffer 2 x 8KB (32768..49151).
// ---------------------------------------------------------------------------
__global__ void __launch_bounds__(256, 2) gemm_qkv_kernel(
    const __half* __restrict__ Wt, const float* __restrict__ Xf, __half* __restrict__ Y,
    const float* __restrict__ bias)
{
    extern __shared__ __align__(16) char smem[];

    const int tid = threadIdx.x;
    const int warp = tid >> 5;
    const int lane = tid & 31;
    const int wm = warp >> 1;
    const int wp = warp & 1;
    const long long b = blockIdx.z;
    const int mbase = blockIdx.x * 128;
    const int p0 = blockIdx.y * 128;
    const __half* Wg = Wt + mbase;                        // [k][768]
    const float* Xg = Xf + b * (long long)C_ * HW_ + p0;  // [k][HW] f32

    const uint32_t sb = smem_u32(smem);
    const uint32_t xb = sb + 32768;

    float acc[2][8][4];
#pragma unroll
    for (int i = 0; i < 2; i++)
#pragma unroll
        for (int j = 0; j < 8; j++)
#pragma unroll
            for (int l = 0; l < 4; l++) acc[i][j][l] = 0.f;

    auto stage_w = [&](int c) {
        const int k0 = c * 32;
        const uint32_t base = sb + (uint32_t)(c & 3) * 8192;
#pragma unroll
        for (int q = 0; q < 2; q++) {
            int sid = tid + q * 256;
            int kr = sid >> 4, s = sid & 15;
            uint32_t sa = base + (uint32_t)kr * 256 + (uint32_t)((s ^ (kr & 7)) << 4);
            cp16(sa, Wg + (long long)(k0 + kr) * 768 + s * 8);
        }
        CP_COMMIT();
    };

    float4 pfx[4];
    auto ldg_x = [&](int c) {
        const int k0 = c * 32;
#pragma unroll
        for (int q = 0; q < 2; q++) {
            int sid = tid + q * 256;
            int kr = sid >> 4, s = sid & 15;
            const float* gp = Xg + (long long)(k0 + kr) * HW_ + s * 8;
            pfx[q * 2]     = *(const float4*)gp;
            pfx[q * 2 + 1] = *(const float4*)(gp + 4);
        }
    };
    auto sts_x = [&](int c) {
        const uint32_t boff = 32768 + (uint32_t)(c & 1) * 8192;
#pragma unroll
        for (int q = 0; q < 2; q++) {
            int sid = tid + q * 256;
            int kr = sid >> 4, s = sid & 15;
            uint4 sv;
            sv.x = packh2(pfx[q * 2].x, pfx[q * 2].y);
            sv.y = packh2(pfx[q * 2].z, pfx[q * 2].w);
            sv.z = packh2(pfx[q * 2 + 1].x, pfx[q * 2 + 1].y);
            sv.w = packh2(pfx[q * 2 + 1].z, pfx[q * 2 + 1].w);
            *(uint4*)(smem + boff + (uint32_t)kr * 256 + (uint32_t)((s ^ (kr & 7)) << 4)) = sv;
        }
    };

    ldg_x(0);
    stage_w(0);
    stage_w(1);
    stage_w(2);

#pragma unroll 1
    for (int c = 0; c < 8; c++) {
        CP_WAIT(2);            // W(c) resident
        sts_x(c);
        if (c < 7) ldg_x(c + 1);
        __syncthreads();       // X visible; all warps done with MMA(c-1)
        const uint32_t wtile = sb + (uint32_t)(c & 3) * 8192;
        const uint32_t xtile = xb + (uint32_t)(c & 1) * 8192;
#pragma unroll
        for (int ks = 0; ks < 2; ks++) {
            const int kb = ks * 16;
            auto faddr = [&](uint32_t tbase, int col0) -> uint32_t {
                int kr = kb + ((lane >> 4) & 1) * 8 + (lane & 7);
                int seg = (col0 >> 3) + ((lane >> 3) & 1);
                return tbase + (uint32_t)kr * 256 + (uint32_t)(((seg ^ (kr & 7)) & 15) << 4);
            };
            uint32_t A[2][4];
            ldsm4t(A[0], faddr(wtile, wm * 32));
            ldsm4t(A[1], faddr(wtile, wm * 32 + 16));
            uint32_t Bf[4][4];
#pragma unroll
            for (int bi = 0; bi < 4; bi++)
                ldsm4t(Bf[bi], faddr(xtile, wp * 64 + bi * 16));
#pragma unroll
            for (int mf = 0; mf < 2; mf++)
#pragma unroll
                for (int nf = 0; nf < 8; nf++)
                    mma16816(acc[mf][nf], A[mf], Bf[nf >> 1][nf & 1], Bf[nf >> 1][(nf & 1) + 2]);
        }
        if (c + 3 < 8) stage_w(c + 3);
        else CP_COMMIT();
    }

    const int gr = lane >> 2, tg = lane & 3;
    const long long ybase = b * (long long)768 * HW_;
#pragma unroll
    for (int mf = 0; mf < 2; mf++) {
        const int m0 = mbase + wm * 32 + mf * 16 + gr;
        float t0 = __ldg(bias + m0), t1 = __ldg(bias + m0 + 8);
#pragma unroll
        for (int nf = 0; nf < 8; nf++) {
            const int p = p0 + wp * 64 + nf * 8 + tg * 2;
            *(__half2*)(Y + ybase + (long long)m0 * HW_ + p) =
                __floats2half2_rn(acc[mf][nf][0] + t0, acc[mf][nf][1] + t0);
            *(__half2*)(Y + ybase + (long long)(m0 + 8) * HW_ + p) =
                __floats2half2_rn(acc[mf][nf][2] + t1, acc[mf][nf][3] + t1);
        }
    }
}

// ---------------------------------------------------------------------------
// fp16 HMMA GEMM (R7 winner): fp16 X via cp.async ring. gaze (MODE 1) / proj (MODE 2).
// ---------------------------------------------------------------------------
template <int MODE, bool OUTH>
__global__ void __launch_bounds__(256, 2) gemm_h_kernel(
    const __half* __restrict__ Wt, const __half* __restrict__ X, void* __restrict__ Yv,
    int Mtot, long long xbs,
    const float* __restrict__ bng, const float* __restrict__ bnb,
    const float* __restrict__ bnm, const float* __restrict__ bnv)
{
    extern __shared__ __align__(16) char smem[];

    const int tid = threadIdx.x;
    const int warp = tid >> 5;
    const int lane = tid & 31;
    const int wm = warp >> 1;
    const int wp = warp & 1;
    const long long b = blockIdx.z;
    const int mbase = blockIdx.x * 128;
    const int p0 = blockIdx.y * 128;
    const __half* Wg = Wt + mbase;
    const __half* Xg = X + b * xbs + p0;

    const uint32_t sb = smem_u32(smem);

    float acc[2][8][4];
#pragma unroll
    for (int i = 0; i < 2; i++)
#pragma unroll
        for (int j = 0; j < 8; j++)
#pragma unroll
            for (int l = 0; l < 4; l++) acc[i][j][l] = 0.f;

    auto stage = [&](int c) {
        const int k0 = c * 32;
        const uint32_t base = sb + (uint32_t)(c & 3) * 16384;
#pragma unroll
        for (int q = 0; q < 4; q++) {
            int sid = tid + q * 256;
            int tile = sid >> 9, rem = sid & 511;
            int kr = rem >> 4, s = rem & 15;
            uint32_t sa = base + (uint32_t)tile * 8192 + (uint32_t)kr * 256
                        + (uint32_t)((s ^ (kr & 7)) << 4);
            const __half* g = (tile == 0)
                ? Wg + (long long)(k0 + kr) * Mtot + s * 8
                : Xg + (long long)(k0 + kr) * HW_ + s * 8;
            cp16(sa, g);
        }
        CP_COMMIT();
    };

    stage(0);
    stage(1);
    stage(2);

#pragma unroll 1
    for (int c = 0; c < 8; c++) {
        CP_WAIT(2);
        __syncthreads();
        const uint32_t wtile = sb + (uint32_t)(c & 3) * 16384;
        const uint32_t xtile = wtile + 8192;
#pragma unroll
        for (int ks = 0; ks < 2; ks++) {
            const int kb = ks * 16;
            auto faddr = [&](uint32_t tbase, int col0) -> uint32_t {
                int kr = kb + ((lane >> 4) & 1) * 8 + (lane & 7);
                int seg = (col0 >> 3) + ((lane >> 3) & 1);
                return tbase + (uint32_t)kr * 256 + (uint32_t)(((seg ^ (kr & 7)) & 15) << 4);
            };
            uint32_t A[2][4];
            ldsm4t(A[0], faddr(wtile, wm * 32));
            ldsm4t(A[1], faddr(wtile, wm * 32 + 16));
            uint32_t Bf[4][4];
#pragma unroll
            for (int bi = 0; bi < 4; bi++)
                ldsm4t(Bf[bi], faddr(xtile, wp * 64 + bi * 16));
#pragma unroll
            for (int mf = 0; mf < 2; mf++)
#pragma unroll
                for (int nf = 0; nf < 8; nf++)
                    mma16816(acc[mf][nf], A[mf], Bf[nf >> 1][nf & 1], Bf[nf >> 1][(nf & 1) + 2]);
        }
        if (c + 3 < 8) stage(c + 3);
        else CP_COMMIT();
    }

    const int gr = lane >> 2, tg = lane & 3;
    const long long ybase = b * (long long)Mtot * HW_;
    __half* YH = (__half*)Yv;
    float*  YF = (float*)Yv;
#pragma unroll
    for (int mf = 0; mf < 2; mf++) {
        const int m0 = mbase + wm * 32 + mf * 16 + gr;
        float s0 = 0.f, t0 = 0.f, s1 = 0.f, t1 = 0.f;
        if (MODE == 2) {
            s0 = __ldg(bng + m0) * rsqrtf(__ldg(bnv + m0) + 1e-5f);
            t0 = __ldg(bnb + m0) - __ldg(bnm + m0) * s0;
            s1 = __ldg(bng + m0 + 8) * rsqrtf(__ldg(bnv + m0 + 8) + 1e-5f);
            t1 = __ldg(bnb + m0 + 8) - __ldg(bnm + m0 + 8) * s1;
        }
#pragma unroll
        for (int nf = 0; nf < 8; nf++) {
            const int p = p0 + wp * 64 + nf * 8 + tg * 2;
            float2 v0 = make_float2(acc[mf][nf][0], acc[mf][nf][1]);
            float2 v1 = make_float2(acc[mf][nf][2], acc[mf][nf][3]);
            if (MODE == 2) {
                v0.x = fmaf(v0.x, s0, t0); v0.y = fmaf(v0.y, s0, t0);
                v1.x = fmaf(v1.x, s1, t1); v1.y = fmaf(v1.y, s1, t1);
            }
            if (OUTH) {
                *(__half2*)(YH + ybase + (long long)m0 * HW_ + p) = __floats2half2_rn(v0.x, v0.y);
                *(__half2*)(YH + ybase + (long long)(m0 + 8) * HW_ + p) = __floats2half2_rn(v1.x, v1.y);
            } else {
                *(float2*)(YF + ybase + (long long)m0 * HW_ + p) = v0;
                *(float2*)(YF + ybase + (long long)(m0 + 8) * HW_ + p) = v1;
            }
        }
    }
}

// ---------------------------------------------------------------------------
// Window attention via HMMA (R7 winner, standalone).
// ---------------------------------------------------------------------------
#define QK_P  72
#define V_P   264
#define SM_QB 0
#define SM_KB 36864
#define SM_VB 73728
#define SM_BS 107520
#define SM_ATTN_TOTAL 115712

__global__ void __launch_bounds__(512, 1) attn_kernel(
    const __half* __restrict__ qkv, const float* __restrict__ table,
    __half* __restrict__ attn_out)
{
    extern __shared__ __align__(16) char sm[];
    __half* qb = (__half*)(sm + SM_QB);
    __half* kb = (__half*)(sm + SM_KB);
    __half* vb = (__half*)(sm + SM_VB);
    float*  bs = (float*)(sm + SM_BS);

    const int tid = threadIdx.x;
    const int b = blockIdx.y;
    const int strip = blockIdx.x;
    const int wy = strip >> 4, wsx = strip & 15;
    const int c = tid & 255;
    const int hlf = tid >> 8;
    const long long gbase = (long long)b * 768 * HW_ + (long long)(wy * 4) * W_ + wsx * 16;

#pragma unroll
    for (int it = 0; it < 4; it++) {
        int id = tid + it * 512;
        int h = id >> 8, t = (id >> 4) & 15, s = id & 15;
        int idx = ((t >> 2) - (s >> 2) + 3) * 7 + ((t & 3) - (s & 3) + 3);
        bs[id] = __ldg(table + idx * 8 + h);
    }

#pragma unroll
    for (int rr = 0; rr < 2; rr++) {
        int r = hlf * 2 + rr;
        const __half* gq = qkv + gbase + (long long)c * HW_ + r * W_;
#pragma unroll
        for (int seg = 0; seg < 2; seg++) {
            uint4 uq = *(const uint4*)(gq + seg * 8);
            uint4 uk = *(const uint4*)(gq + (long long)256 * HW_ + seg * 8);
            uint4 uv = *(const uint4*)(gq + (long long)512 * HW_ + seg * 8);
            int w0 = seg * 2;
            *(uint2*)(qb + c * QK_P + (w0    ) * 16 + r * 4) = make_uint2(uq.x, uq.y);
            *(uint2*)(qb + c * QK_P + (w0 + 1) * 16 + r * 4) = make_uint2(uq.z, uq.w);
            *(uint2*)(kb + c * QK_P + (w0    ) * 16 + r * 4) = make_uint2(uk.x, uk.y);
            *(uint2*)(kb + c * QK_P + (w0 + 1) * 16 + r * 4) = make_uint2(uk.z, uk.w);
            __half* vh8 = (__half*)&uv;
#pragma unroll
            for (int j = 0; j < 8; j++) {
                int x = seg * 8 + j;
                int wt = (x >> 2) * 16 + r * 4 + (x & 3);
                vb[wt * V_P + c] = vh8[j];
            }
        }
    }
    __syncthreads();

    const int warp = tid >> 5;
    const int lane = tid & 31;
    const int krow_off = ((lane >> 4) & 1) * 8 + (lane & 7);
    const int colsel = (lane >> 3) & 1;
    const int t0 = lane >> 2, t1 = t0 + 8;
    const int sbase = (lane & 3) * 2;
    const float scale = 0.17677669529663687f;
    const uint32_t qbu = smem_u32(qb), kbu = smem_u32(kb), vbu = smem_u32(vb);

#pragma unroll
    for (int ti = 0; ti < 2; ti++) {
        const int task = warp * 2 + ti;
        const int win = task >> 3, head = task & 7;
        const int tb = win * 16;
        const int hb = head * 32;

        uint32_t Aq[2][4], Bk[2][4];
#pragma unroll
        for (int kc = 0; kc < 2; kc++) {
            uint32_t off = (uint32_t)(hb + kc * 16 + krow_off) * (QK_P * 2)
                         + (uint32_t)(tb * 2 + colsel * 16);
            ldsm4t(Aq[kc], qbu + off);
            ldsm4t(Bk[kc], kbu + off);
        }
        float sc0[4] = {0.f, 0.f, 0.f, 0.f}, sc1[4] = {0.f, 0.f, 0.f, 0.f};
#pragma unroll
        for (int kc = 0; kc < 2; kc++) {
            mma16816(sc0, Aq[kc], Bk[kc][0], Bk[kc][2]);
            mma16816(sc1, Aq[kc], Bk[kc][1], Bk[kc][3]);
        }
        const float* bh = bs + head * 256;
        sc0[0] = fmaf(sc0[0], scale, bh[t0 * 16 + sbase]);
        sc0[1] = fmaf(sc0[1], scale, bh[t0 * 16 + sbase + 1]);
        sc0[2] = fmaf(sc0[2], scale, bh[t1 * 16 + sbase]);
        sc0[3] = fmaf(sc0[3], scale, bh[t1 * 16 + sbase + 1]);
        sc1[0] = fmaf(sc1[0], scale, bh[t0 * 16 + 8 + sbase]);
        sc1[1] = fmaf(sc1[1], scale, bh[t0 * 16 + 8 + sbase + 1]);
        sc1[2] = fmaf(sc1[2], scale, bh[t1 * 16 + 8 + sbase]);
        sc1[3] = fmaf(sc1[3], scale, bh[t1 * 16 + 8 + sbase + 1]);

        float m0 = fmaxf(fmaxf(sc0[0], sc0[1]), fmaxf(sc1[0], sc1[1]));
        float m1 = fmaxf(fmaxf(sc0[2], sc0[3]), fmaxf(sc1[2], sc1[3]));
        m0 = fmaxf(m0, __shfl_xor_sync(0xffffffffu, m0, 1));
        m0 = fmaxf(m0, __shfl_xor_sync(0xffffffffu, m0, 2));
        m1 = fmaxf(m1, __shfl_xor_sync(0xffffffffu, m1, 1));
        m1 = fmaxf(m1, __shfl_xor_sync(0xffffffffu, m1, 2));
        sc0[0] = __expf(sc0[0] - m0); sc0[1] = __expf(sc0[1] - m0);
        sc0[2] = __expf(sc0[2] - m1); sc0[3] = __expf(sc0[3] - m1);
        sc1[0] = __expf(sc1[0] - m0); sc1[1] = __expf(sc1[1] - m0);
        sc1[2] = __expf(sc1[2] - m1); sc1[3] = __expf(sc1[3] - m1);
        float u0 = sc0[0] + sc0[1] + sc1[0] + sc1[1];
        float u1 = sc0[2] + sc0[3] + sc1[2] + sc1[3];
        u0 += __shfl_xor_sync(0xffffffffu, u0, 1);
        u0 += __shfl_xor_sync(0xffffffffu, u0, 2);
        u1 += __shfl_xor_sync(0xffffffffu, u1, 1);
        u1 += __shfl_xor_sync(0xffffffffu, u1, 2);
        float inv0 = 1.f / u0, inv1 = 1.f / u1;

        uint32_t Ap[4];
        Ap[0] = packh2(sc0[0] * inv0, sc0[1] * inv0);
        Ap[1] = packh2(sc0[2] * inv1, sc0[3] * inv1);
        Ap[2] = packh2(sc1[0] * inv0, sc1[1] * inv0);
        Ap[3] = packh2(sc1[2] * inv1, sc1[3] * inv1);

#pragma unroll
        for (int nc = 0; nc < 2; nc++) {
            uint32_t Bv[4];
            uint32_t va = vbu + (uint32_t)(tb + krow_off) * (V_P * 2)
                        + (uint32_t)((hb + nc * 16) * 2 + colsel * 16);
            ldsm4t(Bv, va);
            float oc0[4] = {0.f, 0.f, 0.f, 0.f}, oc1[4] = {0.f, 0.f, 0.f, 0.f};
            mma16816(oc0, Ap, Bv[0], Bv[2]);
            mma16816(oc1, Ap, Bv[1], Bv[3]);
            int ch0 = hb + nc * 16 + sbase;
            kb[(ch0    ) * QK_P + tb + t0] = __float2half_rn(oc0[0]);
            kb[(ch0 + 1) * QK_P + tb + t0] = __float2half_rn(oc0[1]);
            kb[(ch0    ) * QK_P + tb + t1] = __float2half_rn(oc0[2]);
            kb[(ch0 + 1) * QK_P + tb + t1] = __float2half_rn(oc0[3]);
            kb[(ch0 + 8) * QK_P + tb + t0] = __float2half_rn(oc1[0]);
            kb[(ch0 + 9) * QK_P + tb + t0] = __float2half_rn(oc1[1]);
            kb[(ch0 + 8) * QK_P + tb + t1] = __float2half_rn(oc1[2]);
            kb[(ch0 + 9) * QK_P + tb + t1] = __float2half_rn(oc1[3]);
        }
    }
    __syncthreads();

#pragma unroll
    for (int rr = 0; rr < 2; rr++) {
        int r = hlf * 2 + rr;
        __half tmp[16];
#pragma unroll
        for (int w = 0; w < 4; w++)
            *(uint2*)(tmp + w * 4) = *(uint2*)(kb + c * QK_P + w * 16 + r * 4);
        __half* dst = attn_out + ((long long)(b * 256 + c)) * HW_
                    + (long long)(wy * 4 + r) * W_ + wsx * 16;
        *(uint4*)(dst)     = *(uint4*)(tmp);
        *(uint4*)(dst + 8) = *(uint4*)(tmp + 8);
    }
}

// ---------------------------------------------------------------------------
// Fused stencil (R9): 8-row register blocking, fp16 I/O.
// ---------------------------------------------------------------------------
#define FROWS 8

__global__ void __launch_bounds__(64) fuse_kernel(
    const __half* __restrict__ attn, const __half* __restrict__ qkv,
    const __half* __restrict__ vg, const float* __restrict__ dw,
    const float* __restrict__ g, const float* __restrict__ bb,
    const float* __restrict__ mm, const float* __restrict__ vv,
    __half* __restrict__ pre)
{
    const int j0 = threadIdx.x << 2;
    const int i0 = blockIdx.y * FROWS;
    const int bc = blockIdx.z;
    const int c = bc & 255;
    const int b = bc >> 8;
    const __half* A  = attn + (long long)bc * HW_;
    const __half* VG = vg + (long long)bc * HW_;
    const __half* V  = qkv + (long long)(b * 768 + 512 + c) * HW_;
    __half* P = pre + (long long)bc * HW_;

    float w9[9];
#pragma unroll
    for (int q = 0; q < 9; q++) w9[q] = __ldg(dw + c * 9 + q);
    const float s  = __ldg(g + c) * rsqrtf(__ldg(vv + c) + 1e-5f);
    const float tt = __ldg(bb + c) - __ldg(mm + c) * s;

    auto loadA = [&](int r) -> float4 {
        if (r < 0 || r > 256) return make_float4(0.f, 0.f, 0.f, 0.f);
        if (r == 256) r = 254;
        return ld4h(A + r * W_ + j0);
    };
    auto loadVG = [&](int r, float* o6) {
        if (r < 0 || r >= H_) {
#pragma unroll
            for (int q = 0; q < 6; q++) o6[q] = 0.f;
            return;
        }
        o6[0] = (j0 > 0) ? __half2float(VG[r * W_ + j0 - 1]) : 0.f;
        float4 ct = ld4h(VG + r * W_ + j0);
        o6[1] = ct.x; o6[2] = ct.y; o6[3] = ct.z; o6[4] = ct.w;
        o6[5] = (j0 < 252) ? __half2float(VG[r * W_ + j0 + 4]) : 0.f;
    };

    float4 a_m1 = loadA(i0 - 1), a_0 = loadA(i0), a_p1 = loadA(i0 + 1);
    float vg_m1[6], vg_0[6], vg_p1[6];
    loadVG(i0 - 1, vg_m1);
    loadVG(i0, vg_0);

#pragma unroll
    for (int di = 0; di < FROWS; di++) {
        const int i = i0 + di;
        float4 a_p2 = loadA(i + 2);
        loadVG(i + 1, vg_p1);

        float4 ax;
        ax.x = a_m1.x + a_0.x + a_p1.x + a_p2.x;
        ax.y = a_m1.y + a_0.y + a_p1.y + a_p2.y;
        ax.z = a_m1.z + a_0.z + a_p1.z + a_p2.z;
        ax.w = a_m1.w + a_0.w + a_p1.w + a_p2.w;

        float c7[7];
        c7[0] = (j0 > 0) ? __half2float(A[i * W_ + j0 - 1]) : 0.f;
        c7[1] = a_0.x; c7[2] = a_0.y; c7[3] = a_0.z; c7[4] = a_0.w;
        if (j0 < 252) {
            __half2 rr = *(const __half2*)(A + i * W_ + j0 + 4);
            float2 fr = __half22float2(rr);
            c7[5] = fr.x; c7[6] = fr.y;
        } else {
            c7[5] = a_0.z; c7[6] = 0.f;
        }
        float4 ay;
        ay.x = c7[0] + c7[1] + c7[2] + c7[3];
        ay.y = c7[1] + c7[2] + c7[3] + c7[4];
        ay.z = c7[2] + c7[3] + c7[4] + c7[5];
        ay.w = c7[3] + c7[4] + c7[5] + c7[6];

        float cv[4] = {0.f, 0.f, 0.f, 0.f};
#pragma unroll
        for (int l = 0; l < 4; l++) {
            cv[l] = fmaf(w9[0], vg_m1[l], fmaf(w9[1], vg_m1[l + 1], fmaf(w9[2], vg_m1[l + 2], cv[l])));
            cv[l] = fmaf(w9[3], vg_0[l],  fmaf(w9[4], vg_0[l + 1],  fmaf(w9[5], vg_0[l + 2],  cv[l])));
            cv[l] = fmaf(w9[6], vg_p1[l], fmaf(w9[7], vg_p1[l + 1], fmaf(w9[8], vg_p1[l + 2], cv[l])));
        }

        float4 v4 = ld4h(V + i * W_ + j0);
        st4h(P + i * W_ + j0,
             (ax.x + ay.x) * 0.25f + v4.x + fmaf(cv[0], s, tt),
             (ax.y + ay.y) * 0.25f + v4.y + fmaf(cv[1], s, tt),
             (ax.z + ay.z) * 0.25f + v4.z + fmaf(cv[2], s, tt),
             (ax.w + ay.w) * 0.25f + v4.w + fmaf(cv[3], s, tt));

        a_m1 = a_0; a_0 = a_p1; a_p1 = a_p2;
#pragma unroll
        for (int q = 0; q < 6; q++) { vg_m1[q] = vg_0[q]; vg_0[q] = vg_p1[q]; }
    }
}

// ---------------------------------------------------------------------------
extern "C" void kernel_launch(void* const* d_in, const int* in_sizes, int n_in,
                              void* d_out, int out_size)
{
    const float* x        = (const float*)d_in[0];
    const float* qkv_w    = (const float*)d_in[1];
    const float* qkv_b    = (const float*)d_in[2];
    const float* rel_tab  = (const float*)d_in[3];
    const float* gaze_pw  = (const float*)d_in[4];
    const float* gaze_dw  = (const float*)d_in[5];
    const float* gbn_g    = (const float*)d_in[6];
    const float* gbn_b    = (const float*)d_in[7];
    const float* gbn_m    = (const float*)d_in[8];
    const float* gbn_v    = (const float*)d_in[9];
    const float* proj_w   = (const float*)d_in[10];
    const float* pbn_g    = (const float*)d_in[11];
    const float* pbn_b    = (const float*)d_in[12];
    const float* pbn_m    = (const float*)d_in[13];
    const float* pbn_v    = (const float*)d_in[14];
    float* out = (float*)d_out;

    __half *qkvh, *attnh, *vgh, *preh, *wtq, *wtg, *wtp;
    cudaGetSymbolAddress((void**)&qkvh, d_qkvh_);
    cudaGetSymbolAddress((void**)&attnh, d_attnh_);
    cudaGetSymbolAddress((void**)&vgh, d_vgh_);
    cudaGetSymbolAddress((void**)&preh, d_preh_);
    cudaGetSymbolAddress((void**)&wtq, d_wtq_);
    cudaGetSymbolAddress((void**)&wtg, d_wtg_);
    cudaGetSymbolAddress((void**)&wtp, d_wtp_);

    const int SMEM = 65536;
    const int SMEM_QKV = 49152;
    cudaFuncSetAttribute(gemm_qkv_kernel, cudaFuncAttributeMaxDynamicSharedMemorySize, SMEM_QKV);
    cudaFuncSetAttribute(gemm_h_kernel<1, true>, cudaFuncAttributeMaxDynamicSharedMemorySize, SMEM);
    cudaFuncSetAttribute(gemm_h_kernel<2, false>, cudaFuncAttributeMaxDynamicSharedMemorySize, SMEM);
    cudaFuncSetAttribute(attn_kernel, cudaFuncAttributeMaxDynamicSharedMemorySize, SM_ATTN_TOTAL);

    // 0) weight transposes
    prepass_kernel<<<1280, 256>>>(qkv_w, gaze_pw, proj_w, wtq, wtg, wtp);

    // 1) qkv(fp16) = qkv_w @ x + b   (x staged directly from fp32)
    gemm_qkv_kernel<<<dim3(768 / 128, HW_ / 128, B_), 256, SMEM_QKV>>>(
        wtq, x, qkvh, qkv_b);

    // 2) window attention (HMMA)
    attn_kernel<<<dim3(1024, B_), 512, SM_ATTN_TOTAL>>>(qkvh, rel_tab, attnh);

    // 3) vg(fp16) = gaze_pw @ v (in-place slice of qkv)
    gemm_h_kernel<1, true><<<dim3(256 / 128, HW_ / 128, B_), 256, SMEM>>>(
        wtg, qkvh + (long long)512 * HW_, vgh, 256, (long long)768 * HW_,
        nullptr, nullptr, nullptr, nullptr);

    // 4) pre(fp16) = (ax+ay)/4 + v + BN(dw3x3(vg))
    fuse_kernel<<<dim3(1, H_ / FROWS, B_ * C_), 64>>>(
        attnh, qkvh, vgh, gaze_dw, gbn_g, gbn_b, gbn_m, gbn_v, preh);

    // 5) out(fp32) = BN(proj_w @ pre)
    gemm_h_kernel<2, false><<<dim3(256 / 128, HW_ / 128, B_), 256, SMEM>>>(
        wtp, preh, out, 256, (long long)C_ * HW_,
        pbn_g, pbn_b, pbn_m, pbn_v);
}

// round 15
// speedup vs baseline: 1.0253x; 1.0253x over previous
#include <cuda_runtime.h>
#include <cuda_fp16.h>
#include <cstdint>

#define B_   4
#define C_   256
#define H_   256
#define W_   256
#define HW_  65536

// Scratch (device globals; uint4 for 16B alignment)
__device__ uint4 d_qkvh_[(long long)B_ * 768 * HW_ / 8];
__device__ uint4 d_attnh_[(long long)B_ * C_ * HW_ / 8];
__device__ uint4 d_vgh_[(long long)B_ * C_ * HW_ / 8];
__device__ uint4 d_preh_[(long long)B_ * C_ * HW_ / 8];
__device__ uint4 d_wtq_[768 * 256 / 8];
__device__ uint4 d_wtg_[256 * 256 / 8];
__device__ uint4 d_wtp_[256 * 256 / 8];

// ---------------------------------------------------------------------------
__device__ __forceinline__ uint32_t smem_u32(const void* p) {
    uint32_t a;
    asm("{ .reg .u64 t; cvta.to.shared.u64 t, %1; cvt.u32.u64 %0, t; }" : "=r"(a) : "l"(p));
    return a;
}
__device__ __forceinline__ void cp16(uint32_t s, const void* g) {
    asm volatile("cp.async.cg.shared.global [%0], [%1], 16;" :: "r"(s), "l"(g));
}
#define CP_COMMIT() asm volatile("cp.async.commit_group;" ::: "memory")
#define CP_WAIT(N)  asm volatile("cp.async.wait_group %0;" :: "n"(N) : "memory")

__device__ __forceinline__ void ldsm4t(uint32_t* r, uint32_t a) {
    asm volatile("ldmatrix.sync.aligned.m8n8.x4.trans.shared.b16 {%0,%1,%2,%3}, [%4];"
                 : "=r"(r[0]), "=r"(r[1]), "=r"(r[2]), "=r"(r[3]) : "r"(a));
}
__device__ __forceinline__ void mma16816(float* d, const uint32_t* a, uint32_t b0, uint32_t b1) {
    asm volatile(
        "mma.sync.aligned.m16n8k16.row.col.f32.f16.f16.f32 "
        "{%0,%1,%2,%3}, {%4,%5,%6,%7}, {%8,%9}, {%0,%1,%2,%3};"
        : "+f"(d[0]), "+f"(d[1]), "+f"(d[2]), "+f"(d[3])
        : "r"(a[0]), "r"(a[1]), "r"(a[2]), "r"(a[3]), "r"(b0), "r"(b1));
}
__device__ __forceinline__ float4 ld4h(const __half* p) {
    uint2 u = *(const uint2*)p;
    __half2 a = *(__half2*)&u.x;
    __half2 b = *(__half2*)&u.y;
    float2 fa = __half22float2(a), fb = __half22float2(b);
    return make_float4(fa.x, fa.y, fb.x, fb.y);
}
__device__ __forceinline__ void st4h(__half* p, float x, float y, float z, float w) {
    uint2 u;
    *(__half2*)&u.x = __floats2half2_rn(x, y);
    *(__half2*)&u.y = __floats2half2_rn(z, w);
    *(uint2*)p = u;
}
__device__ __forceinline__ uint32_t packh2(float a, float b) {
    __half2 h = __floats2half2_rn(a, b);
    return *(uint32_t*)&h;
}

// ---------------------------------------------------------------------------
// Pre-pass: weight transposes only
// ---------------------------------------------------------------------------
__global__ void __launch_bounds__(256) prepass_kernel(
    const float* __restrict__ qkv_w, const float* __restrict__ gaze_pw,
    const float* __restrict__ proj_w,
    __half* __restrict__ wtq, __half* __restrict__ wtg, __half* __restrict__ wtp)
{
    int i = blockIdx.x * 256 + threadIdx.x;
    if (i < 196608) {
        int k = i / 768, m = i - k * 768;
        wtq[i] = __float2half_rn(qkv_w[m * 256 + k]);
    } else if (i < 262144) {
        int j = i - 196608;
        int k = j >> 8, m = j & 255;
        wtg[j] = __float2half_rn(gaze_pw[m * 256 + k]);
    } else {
        int j = i - 262144;
        int k = j >> 8, m = j & 255;
        wtp[j] = __float2half_rn(proj_w[m * 256 + k]);
    }
}

// ---------------------------------------------------------------------------
// qkv GEMM with fused f32->f16 X conversion, fully pipelined (race fixed).
// smem (112KB): W ring 4x8KB [0,32768); Xf32 ring 4x16KB [32768,98304);
//               Xf16 double 2x8KB [98304,114688).
// Per chunk: CP_WAIT(2) -> sync -> convert -> sync -> MMA -> stage(c+3).
// ---------------------------------------------------------------------------
#define QKV_SMEM 114688

__global__ void __launch_bounds__(256, 2) gemm_qkv_kernel(
    const __half* __restrict__ Wt, const float* __restrict__ Xf, __half* __restrict__ Y,
    const float* __restrict__ bias)
{
    extern __shared__ __align__(16) char smem[];

    const int tid = threadIdx.x;
    const int warp = tid >> 5;
    const int lane = tid & 31;
    const int wm = warp >> 1;
    const int wp = warp & 1;
    const long long b = blockIdx.z;
    const int mbase = blockIdx.x * 128;
    const int p0 = blockIdx.y * 128;
    const __half* Wg = Wt + mbase;                        // [k][768]
    const float* Xg = Xf + b * (long long)C_ * HW_ + p0;  // [k][HW] f32

    const uint32_t sb = smem_u32(smem);

    float acc[2][8][4];
#pragma unroll
    for (int i = 0; i < 2; i++)
#pragma unroll
        for (int j = 0; j < 8; j++)
#pragma unroll
            for (int l = 0; l < 4; l++) acc[i][j][l] = 0.f;

    auto stage = [&](int c) {
        const int k0 = c * 32;
        const uint32_t wbase = sb + (uint32_t)(c & 3) * 8192;
#pragma unroll
        for (int q = 0; q < 2; q++) {
            int sid = tid + q * 256;
            int kr = sid >> 4, s = sid & 15;
            uint32_t sa = wbase + (uint32_t)kr * 256 + (uint32_t)((s ^ (kr & 7)) << 4);
            cp16(sa, Wg + (long long)(k0 + kr) * 768 + s * 8);
        }
        const uint32_t xbase = sb + 32768 + (uint32_t)(c & 3) * 16384;
#pragma unroll
        for (int q = 0; q < 4; q++) {
            int sid = tid + q * 256;          // 0..1023
            int kr = sid >> 5, s = sid & 31;  // 32 rows x 32 segs(16B)
            cp16(xbase + (uint32_t)kr * 512 + (uint32_t)(s << 4),
                 Xg + (long long)(k0 + kr) * HW_ + s * 4);
        }
        CP_COMMIT();
    };

    stage(0);
    stage(1);
    stage(2);

#pragma unroll 1
    for (int c = 0; c < 8; c++) {
        CP_WAIT(2);            // chunk c (W + Xf32) landed (this thread's copies)
        __syncthreads();       // make ALL threads' cp.async data visible
        // convert Xf32(c) -> Xf16 buffer (c&1): 16 floats per thread
        {
            const char* xs = smem + 32768 + (uint32_t)(c & 3) * 16384;
            char* xd = smem + 98304 + (uint32_t)(c & 1) * 8192;
#pragma unroll
            for (int q = 0; q < 2; q++) {
                int sid = tid + q * 256;
                int kr = sid >> 4, s = sid & 15;   // s: 16B fp16 seg = 8 px = 32B f32
                float4 f0 = *(const float4*)(xs + kr * 512 + s * 32);
                float4 f1 = *(const float4*)(xs + kr * 512 + s * 32 + 16);
                uint4 sv;
                sv.x = packh2(f0.x, f0.y);
                sv.y = packh2(f0.z, f0.w);
                sv.z = packh2(f1.x, f1.y);
                sv.w = packh2(f1.z, f1.w);
                *(uint4*)(xd + kr * 256 + ((s ^ (kr & 7)) << 4)) = sv;
            }
        }
        __syncthreads();       // converted Xf16(c) visible to all warps
        const uint32_t wtile = sb + (uint32_t)(c & 3) * 8192;
        const uint32_t xtile = sb + 98304 + (uint32_t)(c & 1) * 8192;
#pragma unroll
        for (int ks = 0; ks < 2; ks++) {
            const int kb = ks * 16;
            auto faddr = [&](uint32_t tbase, int col0) -> uint32_t {
                int kr = kb + ((lane >> 4) & 1) * 8 + (lane & 7);
                int seg = (col0 >> 3) + ((lane >> 3) & 1);
                return tbase + (uint32_t)kr * 256 + (uint32_t)(((seg ^ (kr & 7)) & 15) << 4);
            };
            uint32_t A[2][4];
            ldsm4t(A[0], faddr(wtile, wm * 32));
            ldsm4t(A[1], faddr(wtile, wm * 32 + 16));
            uint32_t Bf[4][4];
#pragma unroll
            for (int bi = 0; bi < 4; bi++)
                ldsm4t(Bf[bi], faddr(xtile, wp * 64 + bi * 16));
#pragma unroll
            for (int mf = 0; mf < 2; mf++)
#pragma unroll
                for (int nf = 0; nf < 8; nf++)
                    mma16816(acc[mf][nf], A[mf], Bf[nf >> 1][nf & 1], Bf[nf >> 1][(nf & 1) + 2]);
        }
        if (c + 3 < 8) stage(c + 3);
        else CP_COMMIT();
    }

    const int gr = lane >> 2, tg = lane & 3;
    const long long ybase = b * (long long)768 * HW_;
#pragma unroll
    for (int mf = 0; mf < 2; mf++) {
        const int m0 = mbase + wm * 32 + mf * 16 + gr;
        float t0 = __ldg(bias + m0), t1 = __ldg(bias + m0 + 8);
#pragma unroll
        for (int nf = 0; nf < 8; nf++) {
            const int p = p0 + wp * 64 + nf * 8 + tg * 2;
            *(__half2*)(Y + ybase + (long long)m0 * HW_ + p) =
                __floats2half2_rn(acc[mf][nf][0] + t0, acc[mf][nf][1] + t0);
            *(__half2*)(Y + ybase + (long long)(m0 + 8) * HW_ + p) =
                __floats2half2_rn(acc[mf][nf][2] + t1, acc[mf][nf][3] + t1);
        }
    }
}

// ---------------------------------------------------------------------------
// fp16 HMMA GEMM (R7 winner): gaze (MODE 1) / proj (MODE 2).
// ---------------------------------------------------------------------------
template <int MODE, bool OUTH>
__global__ void __launch_bounds__(256, 2) gemm_h_kernel(
    const __half* __restrict__ Wt, const __half* __restrict__ X, void* __restrict__ Yv,
    int Mtot, long long xbs,
    const float* __restrict__ bng, const float* __restrict__ bnb,
    const float* __restrict__ bnm, const float* __restrict__ bnv)
{
    extern __shared__ __align__(16) char smem[];

    const int tid = threadIdx.x;
    const int warp = tid >> 5;
    const int lane = tid & 31;
    const int wm = warp >> 1;
    const int wp = warp & 1;
    const long long b = blockIdx.z;
    const int mbase = blockIdx.x * 128;
    const int p0 = blockIdx.y * 128;
    const __half* Wg = Wt + mbase;
    const __half* Xg = X + b * xbs + p0;

    const uint32_t sb = smem_u32(smem);

    float acc[2][8][4];
#pragma unroll
    for (int i = 0; i < 2; i++)
#pragma unroll
        for (int j = 0; j < 8; j++)
#pragma unroll
            for (int l = 0; l < 4; l++) acc[i][j][l] = 0.f;

    auto stage = [&](int c) {
        const int k0 = c * 32;
        const uint32_t base = sb + (uint32_t)(c & 3) * 16384;
#pragma unroll
        for (int q = 0; q < 4; q++) {
            int sid = tid + q * 256;
            int tile = sid >> 9, rem = sid & 511;
            int kr = rem >> 4, s = rem & 15;
            uint32_t sa = base + (uint32_t)tile * 8192 + (uint32_t)kr * 256
                        + (uint32_t)((s ^ (kr & 7)) << 4);
            const __half* g = (tile == 0)
                ? Wg + (long long)(k0 + kr) * Mtot + s * 8
                : Xg + (long long)(k0 + kr) * HW_ + s * 8;
            cp16(sa, g);
        }
        CP_COMMIT();
    };

    stage(0);
    stage(1);
    stage(2);

#pragma unroll 1
    for (int c = 0; c < 8; c++) {
        CP_WAIT(2);
        __syncthreads();
        const uint32_t wtile = sb + (uint32_t)(c & 3) * 16384;
        const uint32_t xtile = wtile + 8192;
#pragma unroll
        for (int ks = 0; ks < 2; ks++) {
            const int kb = ks * 16;
            auto faddr = [&](uint32_t tbase, int col0) -> uint32_t {
                int kr = kb + ((lane >> 4) & 1) * 8 + (lane & 7);
                int seg = (col0 >> 3) + ((lane >> 3) & 1);
                return tbase + (uint32_t)kr * 256 + (uint32_t)(((seg ^ (kr & 7)) & 15) << 4);
            };
            uint32_t A[2][4];
            ldsm4t(A[0], faddr(wtile, wm * 32));
            ldsm4t(A[1], faddr(wtile, wm * 32 + 16));
            uint32_t Bf[4][4];
#pragma unroll
            for (int bi = 0; bi < 4; bi++)
                ldsm4t(Bf[bi], faddr(xtile, wp * 64 + bi * 16));
#pragma unroll
            for (int mf = 0; mf < 2; mf++)
#pragma unroll
                for (int nf = 0; nf < 8; nf++)
                    mma16816(acc[mf][nf], A[mf], Bf[nf >> 1][nf & 1], Bf[nf >> 1][(nf & 1) + 2]);
        }
        if (c + 3 < 8) stage(c + 3);
        else CP_COMMIT();
    }

    const int gr = lane >> 2, tg = lane & 3;
    const long long ybase = b * (long long)Mtot * HW_;
    __half* YH = (__half*)Yv;
    float*  YF = (float*)Yv;
#pragma unroll
    for (int mf = 0; mf < 2; mf++) {
        const int m0 = mbase + wm * 32 + mf * 16 + gr;
        float s0 = 0.f, t0 = 0.f, s1 = 0.f, t1 = 0.f;
        if (MODE == 2) {
            s0 = __ldg(bng + m0) * rsqrtf(__ldg(bnv + m0) + 1e-5f);
            t0 = __ldg(bnb + m0) - __ldg(bnm + m0) * s0;
            s1 = __ldg(bng + m0 + 8) * rsqrtf(__ldg(bnv + m0 + 8) + 1e-5f);
            t1 = __ldg(bnb + m0 + 8) - __ldg(bnm + m0 + 8) * s1;
        }
#pragma unroll
        for (int nf = 0; nf < 8; nf++) {
            const int p = p0 + wp * 64 + nf * 8 + tg * 2;
            float2 v0 = make_float2(acc[mf][nf][0], acc[mf][nf][1]);
            float2 v1 = make_float2(acc[mf][nf][2], acc[mf][nf][3]);
            if (MODE == 2) {
                v0.x = fmaf(v0.x, s0, t0); v0.y = fmaf(v0.y, s0, t0);
                v1.x = fmaf(v1.x, s1, t1); v1.y = fmaf(v1.y, s1, t1);
            }
            if (OUTH) {
                *(__half2*)(YH + ybase + (long long)m0 * HW_ + p) = __floats2half2_rn(v0.x, v0.y);
                *(__half2*)(YH + ybase + (long long)(m0 + 8) * HW_ + p) = __floats2half2_rn(v1.x, v1.y);
            } else {
                *(float2*)(YF + ybase + (long long)m0 * HW_ + p) = v0;
                *(float2*)(YF + ybase + (long long)(m0 + 8) * HW_ + p) = v1;
            }
        }
    }
}

// ---------------------------------------------------------------------------
// Window attention via HMMA (R7 winner, standalone).
// ---------------------------------------------------------------------------
#define QK_P  72
#define V_P   264
#define SM_QB 0
#define SM_KB 36864
#define SM_VB 73728
#define SM_BS 107520
#define SM_ATTN_TOTAL 115712

__global__ void __launch_bounds__(512, 1) attn_kernel(
    const __half* __restrict__ qkv, const float* __restrict__ table,
    __half* __restrict__ attn_out)
{
    extern __shared__ __align__(16) char sm[];
    __half* qb = (__half*)(sm + SM_QB);
    __half* kb = (__half*)(sm + SM_KB);
    __half* vb = (__half*)(sm + SM_VB);
    float*  bs = (float*)(sm + SM_BS);

    const int tid = threadIdx.x;
    const int b = blockIdx.y;
    const int strip = blockIdx.x;
    const int wy = strip >> 4, wsx = strip & 15;
    const int c = tid & 255;
    const int hlf = tid >> 8;
    const long long gbase = (long long)b * 768 * HW_ + (long long)(wy * 4) * W_ + wsx * 16;

#pragma unroll
    for (int it = 0; it < 4; it++) {
        int id = tid + it * 512;
        int h = id >> 8, t = (id >> 4) & 15, s = id & 15;
        int idx = ((t >> 2) - (s >> 2) + 3) * 7 + ((t & 3) - (s & 3) + 3);
        bs[id] = __ldg(table + idx * 8 + h);
    }

#pragma unroll
    for (int rr = 0; rr < 2; rr++) {
        int r = hlf * 2 + rr;
        const __half* gq = qkv + gbase + (long long)c * HW_ + r * W_;
#pragma unroll
        for (int seg = 0; seg < 2; seg++) {
            uint4 uq = *(const uint4*)(gq + seg * 8);
            uint4 uk = *(const uint4*)(gq + (long long)256 * HW_ + seg * 8);
            uint4 uv = *(const uint4*)(gq + (long long)512 * HW_ + seg * 8);
            int w0 = seg * 2;
            *(uint2*)(qb + c * QK_P + (w0    ) * 16 + r * 4) = make_uint2(uq.x, uq.y);
            *(uint2*)(qb + c * QK_P + (w0 + 1) * 16 + r * 4) = make_uint2(uq.z, uq.w);
            *(uint2*)(kb + c * QK_P + (w0    ) * 16 + r * 4) = make_uint2(uk.x, uk.y);
            *(uint2*)(kb + c * QK_P + (w0 + 1) * 16 + r * 4) = make_uint2(uk.z, uk.w);
            __half* vh8 = (__half*)&uv;
#pragma unroll
            for (int j = 0; j < 8; j++) {
                int x = seg * 8 + j;
                int wt = (x >> 2) * 16 + r * 4 + (x & 3);
                vb[wt * V_P + c] = vh8[j];
            }
        }
    }
    __syncthreads();

    const int warp = tid >> 5;
    const int lane = tid & 31;
    const int krow_off = ((lane >> 4) & 1) * 8 + (lane & 7);
    const int colsel = (lane >> 3) & 1;
    const int t0 = lane >> 2, t1 = t0 + 8;
    const int sbase = (lane & 3) * 2;
    const float scale = 0.17677669529663687f;
    const uint32_t qbu = smem_u32(qb), kbu = smem_u32(kb), vbu = smem_u32(vb);

#pragma unroll
    for (int ti = 0; ti < 2; ti++) {
        const int task = warp * 2 + ti;
        const int win = task >> 3, head = task & 7;
        const int tb = win * 16;
        const int hb = head * 32;

        uint32_t Aq[2][4], Bk[2][4];
#pragma unroll
        for (int kc = 0; kc < 2; kc++) {
            uint32_t off = (uint32_t)(hb + kc * 16 + krow_off) * (QK_P * 2)
                         + (uint32_t)(tb * 2 + colsel * 16);
            ldsm4t(Aq[kc], qbu + off);
            ldsm4t(Bk[kc], kbu + off);
        }
        float sc0[4] = {0.f, 0.f, 0.f, 0.f}, sc1[4] = {0.f, 0.f, 0.f, 0.f};
#pragma unroll
        for (int kc = 0; kc < 2; kc++) {
            mma16816(sc0, Aq[kc], Bk[kc][0], Bk[kc][2]);
            mma16816(sc1, Aq[kc], Bk[kc][1], Bk[kc][3]);
        }
        const float* bh = bs + head * 256;
        sc0[0] = fmaf(sc0[0], scale, bh[t0 * 16 + sbase]);
        sc0[1] = fmaf(sc0[1], scale, bh[t0 * 16 + sbase + 1]);
        sc0[2] = fmaf(sc0[2], scale, bh[t1 * 16 + sbase]);
        sc0[3] = fmaf(sc0[3], scale, bh[t1 * 16 + sbase + 1]);
        sc1[0] = fmaf(sc1[0], scale, bh[t0 * 16 + 8 + sbase]);
        sc1[1] = fmaf(sc1[1], scale, bh[t0 * 16 + 8 + sbase + 1]);
        sc1[2] = fmaf(sc1[2], scale, bh[t1 * 16 + 8 + sbase]);
        sc1[3] = fmaf(sc1[3], scale, bh[t1 * 16 + 8 + sbase + 1]);

        float m0 = fmaxf(fmaxf(sc0[0], sc0[1]), fmaxf(sc1[0], sc1[1]));
        float m1 = fmaxf(fmaxf(sc0[2], sc0[3]), fmaxf(sc1[2], sc1[3]));
        m0 = fmaxf(m0, __shfl_xor_sync(0xffffffffu, m0, 1));
        m0 = fmaxf(m0, __shfl_xor_sync(0xffffffffu, m0, 2));
        m1 = fmaxf(m1, __shfl_xor_sync(0xffffffffu, m1, 1));
        m1 = fmaxf(m1, __shfl_xor_sync(0xffffffffu, m1, 2));
        sc0[0] = __expf(sc0[0] - m0); sc0[1] = __expf(sc0[1] - m0);
        sc0[2] = __expf(sc0[2] - m1); sc0[3] = __expf(sc0[3] - m1);
        sc1[0] = __expf(sc1[0] - m0); sc1[1] = __expf(sc1[1] - m0);
        sc1[2] = __expf(sc1[2] - m1); sc1[3] = __expf(sc1[3] - m1);
        float u0 = sc0[0] + sc0[1] + sc1[0] + sc1[1];
        float u1 = sc0[2] + sc0[3] + sc1[2] + sc1[3];
        u0 += __shfl_xor_sync(0xffffffffu, u0, 1);
        u0 += __shfl_xor_sync(0xffffffffu, u0, 2);
        u1 += __shfl_xor_sync(0xffffffffu, u1, 1);
        u1 += __shfl_xor_sync(0xffffffffu, u1, 2);
        float inv0 = 1.f / u0, inv1 = 1.f / u1;

        uint32_t Ap[4];
        Ap[0] = packh2(sc0[0] * inv0, sc0[1] * inv0);
        Ap[1] = packh2(sc0[2] * inv1, sc0[3] * inv1);
        Ap[2] = packh2(sc1[0] * inv0, sc1[1] * inv0);
        Ap[3] = packh2(sc1[2] * inv1, sc1[3] * inv1);

#pragma unroll
        for (int nc = 0; nc < 2; nc++) {
            uint32_t Bv[4];
            uint32_t va = vbu + (uint32_t)(tb + krow_off) * (V_P * 2)
                        + (uint32_t)((hb + nc * 16) * 2 + colsel * 16);
            ldsm4t(Bv, va);
            float oc0[4] = {0.f, 0.f, 0.f, 0.f}, oc1[4] = {0.f, 0.f, 0.f, 0.f};
            mma16816(oc0, Ap, Bv[0], Bv[2]);
            mma16816(oc1, Ap, Bv[1], Bv[3]);
            int ch0 = hb + nc * 16 + sbase;
            kb[(ch0    ) * QK_P + tb + t0] = __float2half_rn(oc0[0]);
            kb[(ch0 + 1) * QK_P + tb + t0] = __float2half_rn(oc0[1]);
            kb[(ch0    ) * QK_P + tb + t1] = __float2half_rn(oc0[2]);
            kb[(ch0 + 1) * QK_P + tb + t1] = __float2half_rn(oc0[3]);
            kb[(ch0 + 8) * QK_P + tb + t0] = __float2half_rn(oc1[0]);
            kb[(ch0 + 9) * QK_P + tb + t0] = __float2half_rn(oc1[1]);
            kb[(ch0 + 8) * QK_P + tb + t1] = __float2half_rn(oc1[2]);
            kb[(ch0 + 9) * QK_P + tb + t1] = __float2half_rn(oc1[3]);
        }
    }
    __syncthreads();

#pragma unroll
    for (int rr = 0; rr < 2; rr++) {
        int r = hlf * 2 + rr;
        __half tmp[16];
#pragma unroll
        for (int w = 0; w < 4; w++)
            *(uint2*)(tmp + w * 4) = *(uint2*)(kb + c * QK_P + w * 16 + r * 4);
        __half* dst = attn_out + ((long long)(b * 256 + c)) * HW_
                    + (long long)(wy * 4 + r) * W_ + wsx * 16;
        *(uint4*)(dst)     = *(uint4*)(tmp);
        *(uint4*)(dst + 8) = *(uint4*)(tmp + 8);
    }
}

// ---------------------------------------------------------------------------
// Fused stencil (R9): 8-row register blocking, fp16 I/O.
// ---------------------------------------------------------------------------
#define FROWS 8

__global__ void __launch_bounds__(64) fuse_kernel(
    const __half* __restrict__ attn, const __half* __restrict__ qkv,
    const __half* __restrict__ vg, const float* __restrict__ dw,
    const float* __restrict__ g, const float* __restrict__ bb,
    const float* __restrict__ mm, const float* __restrict__ vv,
    __half* __restrict__ pre)
{
    const int j0 = threadIdx.x << 2;
    const int i0 = blockIdx.y * FROWS;
    const int bc = blockIdx.z;
    const int c = bc & 255;
    const int b = bc >> 8;
    const __half* A  = attn + (long long)bc * HW_;
    const __half* VG = vg + (long long)bc * HW_;
    const __half* V  = qkv + (long long)(b * 768 + 512 + c) * HW_;
    __half* P = pre + (long long)bc * HW_;

    float w9[9];
#pragma unroll
    for (int q = 0; q < 9; q++) w9[q] = __ldg(dw + c * 9 + q);
    const float s  = __ldg(g + c) * rsqrtf(__ldg(vv + c) + 1e-5f);
    const float tt = __ldg(bb + c) - __ldg(mm + c) * s;

    auto loadA = [&](int r) -> float4 {
        if (r < 0 || r > 256) return make_float4(0.f, 0.f, 0.f, 0.f);
        if (r == 256) r = 254;
        return ld4h(A + r * W_ + j0);
    };
    auto loadVG = [&](int r, float* o6) {
        if (r < 0 || r >= H_) {
#pragma unroll
            for (int q = 0; q < 6; q++) o6[q] = 0.f;
            return;
        }
        o6[0] = (j0 > 0) ? __half2float(VG[r * W_ + j0 - 1]) : 0.f;
        float4 ct = ld4h(VG + r * W_ + j0);
        o6[1] = ct.x; o6[2] = ct.y; o6[3] = ct.z; o6[4] = ct.w;
        o6[5] = (j0 < 252) ? __half2float(VG[r * W_ + j0 + 4]) : 0.f;
    };

    float4 a_m1 = loadA(i0 - 1), a_0 = loadA(i0), a_p1 = loadA(i0 + 1);
    float vg_m1[6], vg_0[6], vg_p1[6];
    loadVG(i0 - 1, vg_m1);
    loadVG(i0, vg_0);

#pragma unroll
    for (int di = 0; di < FROWS; di++) {
        const int i = i0 + di;
        float4 a_p2 = loadA(i + 2);
        loadVG(i + 1, vg_p1);

        float4 ax;
        ax.x = a_m1.x + a_0.x + a_p1.x + a_p2.x;
        ax.y = a_m1.y + a_0.y + a_p1.y + a_p2.y;
        ax.z = a_m1.z + a_0.z + a_p1.z + a_p2.z;
        ax.w = a_m1.w + a_0.w + a_p1.w + a_p2.w;

        float c7[7];
        c7[0] = (j0 > 0) ? __half2float(A[i * W_ + j0 - 1]) : 0.f;
        c7[1] = a_0.x; c7[2] = a_0.y; c7[3] = a_0.z; c7[4] = a_0.w;
        if (j0 < 252) {
            __half2 rr = *(const __half2*)(A + i * W_ + j0 + 4);
            float2 fr = __half22float2(rr);
            c7[5] = fr.x; c7[6] = fr.y;
        } else {
            c7[5] = a_0.z; c7[6] = 0.f;
        }
        float4 ay;
        ay.x = c7[0] + c7[1] + c7[2] + c7[3];
        ay.y = c7[1] + c7[2] + c7[3] + c7[4];
        ay.z = c7[2] + c7[3] + c7[4] + c7[5];
        ay.w = c7[3] + c7[4] + c7[5] + c7[6];

        float cv[4] = {0.f, 0.f, 0.f, 0.f};
#pragma unroll
        for (int l = 0; l < 4; l++) {
            cv[l] = fmaf(w9[0], vg_m1[l], fmaf(w9[1], vg_m1[l + 1], fmaf(w9[2], vg_m1[l + 2], cv[l])));
            cv[l] = fmaf(w9[3], vg_0[l],  fmaf(w9[4], vg_0[l + 1],  fmaf(w9[5], vg_0[l + 2],  cv[l])));
            cv[l] = fmaf(w9[6], vg_p1[l], fmaf(w9[7], vg_p1[l + 1], fmaf(w9[8], vg_p1[l + 2], cv[l])));
        }

        float4 v4 = ld4h(V + i * W_ + j0);
        st4h(P + i * W_ + j0,
             (ax.x + ay.x) * 0.25f + v4.x + fmaf(cv[0], s, tt),
             (ax.y + ay.y) * 0.25f + v4.y + fmaf(cv[1], s, tt),
             (ax.z + ay.z) * 0.25f + v4.z + fmaf(cv[2], s, tt),
             (ax.w + ay.w) * 0.25f + v4.w + fmaf(cv[3], s, tt));

        a_m1 = a_0; a_0 = a_p1; a_p1 = a_p2;
#pragma unroll
        for (int q = 0; q < 6; q++) { vg_m1[q] = vg_0[q]; vg_0[q] = vg_p1[q]; }
    }
}

// ---------------------------------------------------------------------------
extern "C" void kernel_launch(void* const* d_in, const int* in_sizes, int n_in,
                              void* d_out, int out_size)
{
    const float* x        = (const float*)d_in[0];
    const float* qkv_w    = (const float*)d_in[1];
    const float* qkv_b    = (const float*)d_in[2];
    const float* rel_tab  = (const float*)d_in[3];
    const float* gaze_pw  = (const float*)d_in[4];
    const float* gaze_dw  = (const float*)d_in[5];
    const float* gbn_g    = (const float*)d_in[6];
    const float* gbn_b    = (const float*)d_in[7];
    const float* gbn_m    = (const float*)d_in[8];
    const float* gbn_v    = (const float*)d_in[9];
    const float* proj_w   = (const float*)d_in[10];
    const float* pbn_g    = (const float*)d_in[11];
    const float* pbn_b    = (const float*)d_in[12];
    const float* pbn_m    = (const float*)d_in[13];
    const float* pbn_v    = (const float*)d_in[14];
    float* out = (float*)d_out;

    __half *qkvh, *attnh, *vgh, *preh, *wtq, *wtg, *wtp;
    cudaGetSymbolAddress((void**)&qkvh, d_qkvh_);
    cudaGetSymbolAddress((void**)&attnh, d_attnh_);
    cudaGetSymbolAddress((void**)&vgh, d_vgh_);
    cudaGetSymbolAddress((void**)&preh, d_preh_);
    cudaGetSymbolAddress((void**)&wtq, d_wtq_);
    cudaGetSymbolAddress((void**)&wtg, d_wtg_);
    cudaGetSymbolAddress((void**)&wtp, d_wtp_);

    const int SMEM = 65536;
    cudaFuncSetAttribute(gemm_qkv_kernel, cudaFuncAttributeMaxDynamicSharedMemorySize, QKV_SMEM);
    cudaFuncSetAttribute(gemm_h_kernel<1, true>, cudaFuncAttributeMaxDynamicSharedMemorySize, SMEM);
    cudaFuncSetAttribute(gemm_h_kernel<2, false>, cudaFuncAttributeMaxDynamicSharedMemorySize, SMEM);
    cudaFuncSetAttribute(attn_kernel, cudaFuncAttributeMaxDynamicSharedMemorySize, SM_ATTN_TOTAL);

    // 0) weight transposes
    prepass_kernel<<<1280, 256>>>(qkv_w, gaze_pw, proj_w, wtq, wtg, wtp);

    // 1) qkv(fp16) = qkv_w @ x + b  (x f32 staged via cp.async ring, converted in smem)
    gemm_qkv_kernel<<<dim3(768 / 128, HW_ / 128, B_), 256, QKV_SMEM>>>(
        wtq, x, qkvh, qkv_b);

    // 2) window attention (HMMA)
    attn_kernel<<<dim3(1024, B_), 512, SM_ATTN_TOTAL>>>(qkvh, rel_tab, attnh);

    // 3) vg(fp16) = gaze_pw @ v (in-place slice of qkv)
    gemm_h_kernel<1, true><<<dim3(256 / 128, HW_ / 128, B_), 256, SMEM>>>(
        wtg, qkvh + (long long)512 * HW_, vgh, 256, (long long)768 * HW_,
        nullptr, nullptr, nullptr, nullptr);

    // 4) pre(fp16) = (ax+ay)/4 + v + BN(dw3x3(vg))
    fuse_kernel<<<dim3(1, H_ / FROWS, B_ * C_), 64>>>(
        attnh, qkvh, vgh, gaze_dw, gbn_g, gbn_b, gbn_m, gbn_v, preh);

    // 5) out(fp32) = BN(proj_w @ pre)
    gemm_h_kernel<2, false><<<dim3(256 / 128, HW_ / 128, B_), 256, SMEM>>>(
        wtp, preh, out, 256, (long long)C_ * HW_,
        pbn_g, pbn_b, pbn_m, pbn_v);
}

// round 16
// speedup vs baseline: 1.0823x; 1.0556x over previous
#include <cuda_runtime.h>
#include <cuda_fp16.h>
#include <cstdint>

#define B_   4
#define C_   256
#define H_   256
#define W_   256
#define HW_  65536

// Scratch (device globals; uint4 for 16B alignment)
__device__ uint4 d_qkvh_[(long long)B_ * 768 * HW_ / 8];
__device__ uint4 d_attnh_[(long long)B_ * C_ * HW_ / 8];
__device__ uint4 d_vgh_[(long long)B_ * C_ * HW_ / 8];
__device__ uint4 d_preh_[(long long)B_ * C_ * HW_ / 8];
__device__ uint4 d_xh_[(long long)B_ * C_ * HW_ / 8];     // fp16 x (written by qkv kernel A)
__device__ uint4 d_wtq_[768 * 256 / 8];
__device__ uint4 d_wtg_[256 * 256 / 8];
__device__ uint4 d_wtp_[256 * 256 / 8];

// ---------------------------------------------------------------------------
__device__ __forceinline__ uint32_t smem_u32(const void* p) {
    uint32_t a;
    asm("{ .reg .u64 t; cvta.to.shared.u64 t, %1; cvt.u32.u64 %0, t; }" : "=r"(a) : "l"(p));
    return a;
}
__device__ __forceinline__ void cp16(uint32_t s, const void* g) {
    asm volatile("cp.async.cg.shared.global [%0], [%1], 16;" :: "r"(s), "l"(g));
}
#define CP_COMMIT() asm volatile("cp.async.commit_group;" ::: "memory")
#define CP_WAIT(N)  asm volatile("cp.async.wait_group %0;" :: "n"(N) : "memory")

__device__ __forceinline__ void ldsm4t(uint32_t* r, uint32_t a) {
    asm volatile("ldmatrix.sync.aligned.m8n8.x4.trans.shared.b16 {%0,%1,%2,%3}, [%4];"
                 : "=r"(r[0]), "=r"(r[1]), "=r"(r[2]), "=r"(r[3]) : "r"(a));
}
__device__ __forceinline__ void mma16816(float* d, const uint32_t* a, uint32_t b0, uint32_t b1) {
    asm volatile(
        "mma.sync.aligned.m16n8k16.row.col.f32.f16.f16.f32 "
        "{%0,%1,%2,%3}, {%4,%5,%6,%7}, {%8,%9}, {%0,%1,%2,%3};"
        : "+f"(d[0]), "+f"(d[1]), "+f"(d[2]), "+f"(d[3])
        : "r"(a[0]), "r"(a[1]), "r"(a[2]), "r"(a[3]), "r"(b0), "r"(b1));
}
__device__ __forceinline__ float4 ld4h(const __half* p) {
    uint2 u = *(const uint2*)p;
    __half2 a = *(__half2*)&u.x;
    __half2 b = *(__half2*)&u.y;
    float2 fa = __half22float2(a), fb = __half22float2(b);
    return make_float4(fa.x, fa.y, fb.x, fb.y);
}
__device__ __forceinline__ void st4h(__half* p, float x, float y, float z, float w) {
    uint2 u;
    *(__half2*)&u.x = __floats2half2_rn(x, y);
    *(__half2*)&u.y = __floats2half2_rn(z, w);
    *(uint2*)p = u;
}
__device__ __forceinline__ uint32_t packh2(float a, float b) {
    __half2 h = __floats2half2_rn(a, b);
    return *(uint32_t*)&h;
}

// ---------------------------------------------------------------------------
// Pre-pass: weight transposes only
// ---------------------------------------------------------------------------
__global__ void __launch_bounds__(256) prepass_kernel(
    const float* __restrict__ qkv_w, const float* __restrict__ gaze_pw,
    const float* __restrict__ proj_w,
    __half* __restrict__ wtq, __half* __restrict__ wtg, __half* __restrict__ wtp)
{
    int i = blockIdx.x * 256 + threadIdx.x;
    if (i < 196608) {
        int k = i / 768, m = i - k * 768;
        wtq[i] = __float2half_rn(qkv_w[m * 256 + k]);
    } else if (i < 262144) {
        int j = i - 196608;
        int k = j >> 8, m = j & 255;
        wtg[j] = __float2half_rn(gaze_pw[m * 256 + k]);
    } else {
        int j = i - 262144;
        int k = j >> 8, m = j & 255;
        wtp[j] = __float2half_rn(proj_w[m * 256 + k]);
    }
}

// ---------------------------------------------------------------------------
// qkv kernel A: m-tile 0 ONLY (channels 0..127), f32 X via cp.async ring with
// in-smem convert; the convert step ALSO streams fp16 X to global (xh).
// Each (k, p) element of X is staged exactly once per (p0, b) -> complete xh.
// smem (112KB): W ring 4x8KB; Xf32 ring 4x16KB; Xf16 double 2x8KB.
// ---------------------------------------------------------------------------
#define QKV_SMEM 114688

__global__ void __launch_bounds__(256, 2) gemm_qkvA_kernel(
    const __half* __restrict__ Wt, const float* __restrict__ Xf,
    __half* __restrict__ Y, __half* __restrict__ xh,
    const float* __restrict__ bias)
{
    extern __shared__ __align__(16) char smem[];

    const int tid = threadIdx.x;
    const int warp = tid >> 5;
    const int lane = tid & 31;
    const int wm = warp >> 1;
    const int wp = warp & 1;
    const long long b = blockIdx.z;
    const int p0 = blockIdx.x * 128;
    const __half* Wg = Wt;                                // mbase = 0, [k][768]
    const float* Xg = Xf + b * (long long)C_ * HW_ + p0;  // [k][HW] f32
    __half* xh_b = xh + b * (long long)C_ * HW_ + p0;

    const uint32_t sb = smem_u32(smem);

    float acc[2][8][4];
#pragma unroll
    for (int i = 0; i < 2; i++)
#pragma unroll
        for (int j = 0; j < 8; j++)
#pragma unroll
            for (int l = 0; l < 4; l++) acc[i][j][l] = 0.f;

    auto stage = [&](int c) {
        const int k0 = c * 32;
        const uint32_t wbase = sb + (uint32_t)(c & 3) * 8192;
#pragma unroll
        for (int q = 0; q < 2; q++) {
            int sid = tid + q * 256;
            int kr = sid >> 4, s = sid & 15;
            uint32_t sa = wbase + (uint32_t)kr * 256 + (uint32_t)((s ^ (kr & 7)) << 4);
            cp16(sa, Wg + (long long)(k0 + kr) * 768 + s * 8);
        }
        const uint32_t xbase = sb + 32768 + (uint32_t)(c & 3) * 16384;
#pragma unroll
        for (int q = 0; q < 4; q++) {
            int sid = tid + q * 256;
            int kr = sid >> 5, s = sid & 31;
            cp16(xbase + (uint32_t)kr * 512 + (uint32_t)(s << 4),
                 Xg + (long long)(k0 + kr) * HW_ + s * 4);
        }
        CP_COMMIT();
    };

    stage(0);
    stage(1);
    stage(2);

#pragma unroll 1
    for (int c = 0; c < 8; c++) {
        CP_WAIT(2);
        __syncthreads();       // cross-thread cp.async visibility
        // convert Xf32(c) -> Xf16 smem buffer (c&1) AND global xh
        {
            const char* xs = smem + 32768 + (uint32_t)(c & 3) * 16384;
            char* xd = smem + 98304 + (uint32_t)(c & 1) * 8192;
            const int k0 = c * 32;
#pragma unroll
            for (int q = 0; q < 2; q++) {
                int sid = tid + q * 256;
                int kr = sid >> 4, s = sid & 15;   // s: 16B fp16 seg = 8 px
                float4 f0 = *(const float4*)(xs + kr * 512 + s * 32);
                float4 f1 = *(const float4*)(xs + kr * 512 + s * 32 + 16);
                uint4 sv;
                sv.x = packh2(f0.x, f0.y);
                sv.y = packh2(f0.z, f0.w);
                sv.z = packh2(f1.x, f1.y);
                sv.w = packh2(f1.z, f1.w);
                *(uint4*)(xd + kr * 256 + ((s ^ (kr & 7)) << 4)) = sv;
                *(uint4*)(xh_b + (long long)(k0 + kr) * HW_ + s * 8) = sv;
            }
        }
        __syncthreads();       // converted Xf16(c) visible to all warps
        const uint32_t wtile = sb + (uint32_t)(c & 3) * 8192;
        const uint32_t xtile = sb + 98304 + (uint32_t)(c & 1) * 8192;
#pragma unroll
        for (int ks = 0; ks < 2; ks++) {
            const int kb = ks * 16;
            auto faddr = [&](uint32_t tbase, int col0) -> uint32_t {
                int kr = kb + ((lane >> 4) & 1) * 8 + (lane & 7);
                int seg = (col0 >> 3) + ((lane >> 3) & 1);
                return tbase + (uint32_t)kr * 256 + (uint32_t)(((seg ^ (kr & 7)) & 15) << 4);
            };
            uint32_t A[2][4];
            ldsm4t(A[0], faddr(wtile, wm * 32));
            ldsm4t(A[1], faddr(wtile, wm * 32 + 16));
            uint32_t Bf[4][4];
#pragma unroll
            for (int bi = 0; bi < 4; bi++)
                ldsm4t(Bf[bi], faddr(xtile, wp * 64 + bi * 16));
#pragma unroll
            for (int mf = 0; mf < 2; mf++)
#pragma unroll
                for (int nf = 0; nf < 8; nf++)
                    mma16816(acc[mf][nf], A[mf], Bf[nf >> 1][nf & 1], Bf[nf >> 1][(nf & 1) + 2]);
        }
        if (c + 3 < 8) stage(c + 3);
        else CP_COMMIT();
    }

    const int gr = lane >> 2, tg = lane & 3;
    const long long ybase = b * (long long)768 * HW_;
#pragma unroll
    for (int mf = 0; mf < 2; mf++) {
        const int m0 = wm * 32 + mf * 16 + gr;
        float t0 = __ldg(bias + m0), t1 = __ldg(bias + m0 + 8);
#pragma unroll
        for (int nf = 0; nf < 8; nf++) {
            const int p = p0 + wp * 64 + nf * 8 + tg * 2;
            *(__half2*)(Y + ybase + (long long)m0 * HW_ + p) =
                __floats2half2_rn(acc[mf][nf][0] + t0, acc[mf][nf][1] + t0);
            *(__half2*)(Y + ybase + (long long)(m0 + 8) * HW_ + p) =
                __floats2half2_rn(acc[mf][nf][2] + t1, acc[mf][nf][3] + t1);
        }
    }
}

// ---------------------------------------------------------------------------
// fp16 HMMA GEMM (R7 winner) + moff: MODE 0 +bias (qkv B), 1 plain (gaze),
// 2 BN (proj). OUTH: fp16 output.
// ---------------------------------------------------------------------------
template <int MODE, bool OUTH>
__global__ void __launch_bounds__(256, 2) gemm_h_kernel(
    const __half* __restrict__ Wt, const __half* __restrict__ X, void* __restrict__ Yv,
    int Mtot, long long xbs, int moff,
    const float* __restrict__ bias,
    const float* __restrict__ bng, const float* __restrict__ bnb,
    const float* __restrict__ bnm, const float* __restrict__ bnv)
{
    extern __shared__ __align__(16) char smem[];

    const int tid = threadIdx.x;
    const int warp = tid >> 5;
    const int lane = tid & 31;
    const int wm = warp >> 1;
    const int wp = warp & 1;
    const long long b = blockIdx.z;
    const int mbase = blockIdx.x * 128 + moff;
    const int p0 = blockIdx.y * 128;
    const __half* Wg = Wt + mbase;
    const __half* Xg = X + b * xbs + p0;

    const uint32_t sb = smem_u32(smem);

    float acc[2][8][4];
#pragma unroll
    for (int i = 0; i < 2; i++)
#pragma unroll
        for (int j = 0; j < 8; j++)
#pragma unroll
            for (int l = 0; l < 4; l++) acc[i][j][l] = 0.f;

    auto stage = [&](int c) {
        const int k0 = c * 32;
        const uint32_t base = sb + (uint32_t)(c & 3) * 16384;
#pragma unroll
        for (int q = 0; q < 4; q++) {
            int sid = tid + q * 256;
            int tile = sid >> 9, rem = sid & 511;
            int kr = rem >> 4, s = rem & 15;
            uint32_t sa = base + (uint32_t)tile * 8192 + (uint32_t)kr * 256
                        + (uint32_t)((s ^ (kr & 7)) << 4);
            const __half* g = (tile == 0)
                ? Wg + (long long)(k0 + kr) * Mtot + s * 8
                : Xg + (long long)(k0 + kr) * HW_ + s * 8;
            cp16(sa, g);
        }
        CP_COMMIT();
    };

    stage(0);
    stage(1);
    stage(2);

#pragma unroll 1
    for (int c = 0; c < 8; c++) {
        CP_WAIT(2);
        __syncthreads();
        const uint32_t wtile = sb + (uint32_t)(c & 3) * 16384;
        const uint32_t xtile = wtile + 8192;
#pragma unroll
        for (int ks = 0; ks < 2; ks++) {
            const int kb = ks * 16;
            auto faddr = [&](uint32_t tbase, int col0) -> uint32_t {
                int kr = kb + ((lane >> 4) & 1) * 8 + (lane & 7);
                int seg = (col0 >> 3) + ((lane >> 3) & 1);
                return tbase + (uint32_t)kr * 256 + (uint32_t)(((seg ^ (kr & 7)) & 15) << 4);
            };
            uint32_t A[2][4];
            ldsm4t(A[0], faddr(wtile, wm * 32));
            ldsm4t(A[1], faddr(wtile, wm * 32 + 16));
            uint32_t Bf[4][4];
#pragma unroll
            for (int bi = 0; bi < 4; bi++)
                ldsm4t(Bf[bi], faddr(xtile, wp * 64 + bi * 16));
#pragma unroll
            for (int mf = 0; mf < 2; mf++)
#pragma unroll
                for (int nf = 0; nf < 8; nf++)
                    mma16816(acc[mf][nf], A[mf], Bf[nf >> 1][nf & 1], Bf[nf >> 1][(nf & 1) + 2]);
        }
        if (c + 3 < 8) stage(c + 3);
        else CP_COMMIT();
    }

    const int gr = lane >> 2, tg = lane & 3;
    const long long ybase = b * (long long)Mtot * HW_;
    __half* YH = (__half*)Yv;
    float*  YF = (float*)Yv;
#pragma unroll
    for (int mf = 0; mf < 2; mf++) {
        const int m0 = mbase + wm * 32 + mf * 16 + gr;
        float s0 = 0.f, t0 = 0.f, s1 = 0.f, t1 = 0.f;
        if (MODE == 0) {
            t0 = __ldg(bias + m0); t1 = __ldg(bias + m0 + 8);
        } else if (MODE == 2) {
            s0 = __ldg(bng + m0) * rsqrtf(__ldg(bnv + m0) + 1e-5f);
            t0 = __ldg(bnb + m0) - __ldg(bnm + m0) * s0;
            s1 = __ldg(bng + m0 + 8) * rsqrtf(__ldg(bnv + m0 + 8) + 1e-5f);
            t1 = __ldg(bnb + m0 + 8) - __ldg(bnm + m0 + 8) * s1;
        }
#pragma unroll
        for (int nf = 0; nf < 8; nf++) {
            const int p = p0 + wp * 64 + nf * 8 + tg * 2;
            float2 v0 = make_float2(acc[mf][nf][0], acc[mf][nf][1]);
            float2 v1 = make_float2(acc[mf][nf][2], acc[mf][nf][3]);
            if (MODE == 0) {
                v0.x += t0; v0.y += t0; v1.x += t1; v1.y += t1;
            } else if (MODE == 2) {
                v0.x = fmaf(v0.x, s0, t0); v0.y = fmaf(v0.y, s0, t0);
                v1.x = fmaf(v1.x, s1, t1); v1.y = fmaf(v1.y, s1, t1);
            }
            if (OUTH) {
                *(__half2*)(YH + ybase + (long long)m0 * HW_ + p) = __floats2half2_rn(v0.x, v0.y);
                *(__half2*)(YH + ybase + (long long)(m0 + 8) * HW_ + p) = __floats2half2_rn(v1.x, v1.y);
            } else {
                *(float2*)(YF + ybase + (long long)m0 * HW_ + p) = v0;
                *(float2*)(YF + ybase + (long long)(m0 + 8) * HW_ + p) = v1;
            }
        }
    }
}

// ---------------------------------------------------------------------------
// Window attention via HMMA (R7 winner, standalone).
// ---------------------------------------------------------------------------
#define QK_P  72
#define V_P   264
#define SM_QB 0
#define SM_KB 36864
#define SM_VB 73728
#define SM_BS 107520
#define SM_ATTN_TOTAL 115712

__global__ void __launch_bounds__(512, 1) attn_kernel(
    const __half* __restrict__ qkv, const float* __restrict__ table,
    __half* __restrict__ attn_out)
{
    extern __shared__ __align__(16) char sm[];
    __half* qb = (__half*)(sm + SM_QB);
    __half* kb = (__half*)(sm + SM_KB);
    __half* vb = (__half*)(sm + SM_VB);
    float*  bs = (float*)(sm + SM_BS);

    const int tid = threadIdx.x;
    const int b = blockIdx.y;
    const int strip = blockIdx.x;
    const int wy = strip >> 4, wsx = strip & 15;
    const int c = tid & 255;
    const int hlf = tid >> 8;
    const long long gbase = (long long)b * 768 * HW_ + (long long)(wy * 4) * W_ + wsx * 16;

#pragma unroll
    for (int it = 0; it < 4; it++) {
        int id = tid + it * 512;
        int h = id >> 8, t = (id >> 4) & 15, s = id & 15;
        int idx = ((t >> 2) - (s >> 2) + 3) * 7 + ((t & 3) - (s & 3) + 3);
        bs[id] = __ldg(table + idx * 8 + h);
    }

#pragma unroll
    for (int rr = 0; rr < 2; rr++) {
        int r = hlf * 2 + rr;
        const __half* gq = qkv + gbase + (long long)c * HW_ + r * W_;
#pragma unroll
        for (int seg = 0; seg < 2; seg++) {
            uint4 uq = *(const uint4*)(gq + seg * 8);
            uint4 uk = *(const uint4*)(gq + (long long)256 * HW_ + seg * 8);
            uint4 uv = *(const uint4*)(gq + (long long)512 * HW_ + seg * 8);
            int w0 = seg * 2;
            *(uint2*)(qb + c * QK_P + (w0    ) * 16 + r * 4) = make_uint2(uq.x, uq.y);
            *(uint2*)(qb + c * QK_P + (w0 + 1) * 16 + r * 4) = make_uint2(uq.z, uq.w);
            *(uint2*)(kb + c * QK_P + (w0    ) * 16 + r * 4) = make_uint2(uk.x, uk.y);
            *(uint2*)(kb + c * QK_P + (w0 + 1) * 16 + r * 4) = make_uint2(uk.z, uk.w);
            __half* vh8 = (__half*)&uv;
#pragma unroll
            for (int j = 0; j < 8; j++) {
                int x = seg * 8 + j;
                int wt = (x >> 2) * 16 + r * 4 + (x & 3);
                vb[wt * V_P + c] = vh8[j];
            }
        }
    }
    __syncthreads();

    const int warp = tid >> 5;
    const int lane = tid & 31;
    const int krow_off = ((lane >> 4) & 1) * 8 + (lane & 7);
    const int colsel = (lane >> 3) & 1;
    const int t0 = lane >> 2, t1 = t0 + 8;
    const int sbase = (lane & 3) * 2;
    const float scale = 0.17677669529663687f;
    const uint32_t qbu = smem_u32(qb), kbu = smem_u32(kb), vbu = smem_u32(vb);

#pragma unroll
    for (int ti = 0; ti < 2; ti++) {
        const int task = warp * 2 + ti;
        const int win = task >> 3, head = task & 7;
        const int tb = win * 16;
        const int hb = head * 32;

        uint32_t Aq[2][4], Bk[2][4];
#pragma unroll
        for (int kc = 0; kc < 2; kc++) {
            uint32_t off = (uint32_t)(hb + kc * 16 + krow_off) * (QK_P * 2)
                         + (uint32_t)(tb * 2 + colsel * 16);
            ldsm4t(Aq[kc], qbu + off);
            ldsm4t(Bk[kc], kbu + off);
        }
        float sc0[4] = {0.f, 0.f, 0.f, 0.f}, sc1[4] = {0.f, 0.f, 0.f, 0.f};
#pragma unroll
        for (int kc = 0; kc < 2; kc++) {
            mma16816(sc0, Aq[kc], Bk[kc][0], Bk[kc][2]);
            mma16816(sc1, Aq[kc], Bk[kc][1], Bk[kc][3]);
        }
        const float* bh = bs + head * 256;
        sc0[0] = fmaf(sc0[0], scale, bh[t0 * 16 + sbase]);
        sc0[1] = fmaf(sc0[1], scale, bh[t0 * 16 + sbase + 1]);
        sc0[2] = fmaf(sc0[2], scale, bh[t1 * 16 + sbase]);
        sc0[3] = fmaf(sc0[3], scale, bh[t1 * 16 + sbase + 1]);
        sc1[0] = fmaf(sc1[0], scale, bh[t0 * 16 + 8 + sbase]);
        sc1[1] = fmaf(sc1[1], scale, bh[t0 * 16 + 8 + sbase + 1]);
        sc1[2] = fmaf(sc1[2], scale, bh[t1 * 16 + 8 + sbase]);
        sc1[3] = fmaf(sc1[3], scale, bh[t1 * 16 + 8 + sbase + 1]);

        float m0 = fmaxf(fmaxf(sc0[0], sc0[1]), fmaxf(sc1[0], sc1[1]));
        float m1 = fmaxf(fmaxf(sc0[2], sc0[3]), fmaxf(sc1[2], sc1[3]));
        m0 = fmaxf(m0, __shfl_xor_sync(0xffffffffu, m0, 1));
        m0 = fmaxf(m0, __shfl_xor_sync(0xffffffffu, m0, 2));
        m1 = fmaxf(m1, __shfl_xor_sync(0xffffffffu, m1, 1));
        m1 = fmaxf(m1, __shfl_xor_sync(0xffffffffu, m1, 2));
        sc0[0] = __expf(sc0[0] - m0); sc0[1] = __expf(sc0[1] - m0);
        sc0[2] = __expf(sc0[2] - m1); sc0[3] = __expf(sc0[3] - m1);
        sc1[0] = __expf(sc1[0] - m0); sc1[1] = __expf(sc1[1] - m0);
        sc1[2] = __expf(sc1[2] - m1); sc1[3] = __expf(sc1[3] - m1);
        float u0 = sc0[0] + sc0[1] + sc1[0] + sc1[1];
        float u1 = sc0[2] + sc0[3] + sc1[2] + sc1[3];
        u0 += __shfl_xor_sync(0xffffffffu, u0, 1);
        u0 += __shfl_xor_sync(0xffffffffu, u0, 2);
        u1 += __shfl_xor_sync(0xffffffffu, u1, 1);
        u1 += __shfl_xor_sync(0xffffffffu, u1, 2);
        float inv0 = 1.f / u0, inv1 = 1.f / u1;

        uint32_t Ap[4];
        Ap[0] = packh2(sc0[0] * inv0, sc0[1] * inv0);
        Ap[1] = packh2(sc0[2] * inv1, sc0[3] * inv1);
        Ap[2] = packh2(sc1[0] * inv0, sc1[1] * inv0);
        Ap[3] = packh2(sc1[2] * inv1, sc1[3] * inv1);

#pragma unroll
        for (int nc = 0; nc < 2; nc++) {
            uint32_t Bv[4];
            uint32_t va = vbu + (uint32_t)(tb + krow_off) * (V_P * 2)
                        + (uint32_t)((hb + nc * 16) * 2 + colsel * 16);
            ldsm4t(Bv, va);
            float oc0[4] = {0.f, 0.f, 0.f, 0.f}, oc1[4] = {0.f, 0.f, 0.f, 0.f};
            mma16816(oc0, Ap, Bv[0], Bv[2]);
            mma16816(oc1, Ap, Bv[1], Bv[3]);
            int ch0 = hb + nc * 16 + sbase;
            kb[(ch0    ) * QK_P + tb + t0] = __float2half_rn(oc0[0]);
            kb[(ch0 + 1) * QK_P + tb + t0] = __float2half_rn(oc0[1]);
            kb[(ch0    ) * QK_P + tb + t1] = __float2half_rn(oc0[2]);
            kb[(ch0 + 1) * QK_P + tb + t1] = __float2half_rn(oc0[3]);
            kb[(ch0 + 8) * QK_P + tb + t0] = __float2half_rn(oc1[0]);
            kb[(ch0 + 9) * QK_P + tb + t0] = __float2half_rn(oc1[1]);
            kb[(ch0 + 8) * QK_P + tb + t1] = __float2half_rn(oc1[2]);
            kb[(ch0 + 9) * QK_P + tb + t1] = __float2half_rn(oc1[3]);
        }
    }
    __syncthreads();

#pragma unroll
    for (int rr = 0; rr < 2; rr++) {
        int r = hlf * 2 + rr;
        __half tmp[16];
#pragma unroll
        for (int w = 0; w < 4; w++)
            *(uint2*)(tmp + w * 4) = *(uint2*)(kb + c * QK_P + w * 16 + r * 4);
        __half* dst = attn_out + ((long long)(b * 256 + c)) * HW_
                    + (long long)(wy * 4 + r) * W_ + wsx * 16;
        *(uint4*)(dst)     = *(uint4*)(tmp);
        *(uint4*)(dst + 8) = *(uint4*)(tmp + 8);
    }
}

// ---------------------------------------------------------------------------
// Fused stencil (R9): 8-row register blocking, fp16 I/O.
// ---------------------------------------------------------------------------
#define FROWS 8

__global__ void __launch_bounds__(64) fuse_kernel(
    const __half* __restrict__ attn, const __half* __restrict__ qkv,
    const __half* __restrict__ vg, const float* __restrict__ dw,
    const float* __restrict__ g, const float* __restrict__ bb,
    const float* __restrict__ mm, const float* __restrict__ vv,
    __half* __restrict__ pre)
{
    const int j0 = threadIdx.x << 2;
    const int i0 = blockIdx.y * FROWS;
    const int bc = blockIdx.z;
    const int c = bc & 255;
    const int b = bc >> 8;
    const __half* A  = attn + (long long)bc * HW_;
    const __half* VG = vg + (long long)bc * HW_;
    const __half* V  = qkv + (long long)(b * 768 + 512 + c) * HW_;
    __half* P = pre + (long long)bc * HW_;

    float w9[9];
#pragma unroll
    for (int q = 0; q < 9; q++) w9[q] = __ldg(dw + c * 9 + q);
    const float s  = __ldg(g + c) * rsqrtf(__ldg(vv + c) + 1e-5f);
    const float tt = __ldg(bb + c) - __ldg(mm + c) * s;

    auto loadA = [&](int r) -> float4 {
        if (r < 0 || r > 256) return make_float4(0.f, 0.f, 0.f, 0.f);
        if (r == 256) r = 254;
        return ld4h(A + r * W_ + j0);
    };
    auto loadVG = [&](int r, float* o6) {
        if (r < 0 || r >= H_) {
#pragma unroll
            for (int q = 0; q < 6; q++) o6[q] = 0.f;
            return;
        }
        o6[0] = (j0 > 0) ? __half2float(VG[r * W_ + j0 - 1]) : 0.f;
        float4 ct = ld4h(VG + r * W_ + j0);
        o6[1] = ct.x; o6[2] = ct.y; o6[3] = ct.z; o6[4] = ct.w;
        o6[5] = (j0 < 252) ? __half2float(VG[r * W_ + j0 + 4]) : 0.f;
    };

    float4 a_m1 = loadA(i0 - 1), a_0 = loadA(i0), a_p1 = loadA(i0 + 1);
    float vg_m1[6], vg_0[6], vg_p1[6];
    loadVG(i0 - 1, vg_m1);
    loadVG(i0, vg_0);

#pragma unroll
    for (int di = 0; di < FROWS; di++) {
        const int i = i0 + di;
        float4 a_p2 = loadA(i + 2);
        loadVG(i + 1, vg_p1);

        float4 ax;
        ax.x = a_m1.x + a_0.x + a_p1.x + a_p2.x;
        ax.y = a_m1.y + a_0.y + a_p1.y + a_p2.y;
        ax.z = a_m1.z + a_0.z + a_p1.z + a_p2.z;
        ax.w = a_m1.w + a_0.w + a_p1.w + a_p2.w;

        float c7[7];
        c7[0] = (j0 > 0) ? __half2float(A[i * W_ + j0 - 1]) : 0.f;
        c7[1] = a_0.x; c7[2] = a_0.y; c7[3] = a_0.z; c7[4] = a_0.w;
        if (j0 < 252) {
            __half2 rr = *(const __half2*)(A + i * W_ + j0 + 4);
            float2 fr = __half22float2(rr);
            c7[5] = fr.x; c7[6] = fr.y;
        } else {
            c7[5] = a_0.z; c7[6] = 0.f;
        }
        float4 ay;
        ay.x = c7[0] + c7[1] + c7[2] + c7[3];
        ay.y = c7[1] + c7[2] + c7[3] + c7[4];
        ay.z = c7[2] + c7[3] + c7[4] + c7[5];
        ay.w = c7[3] + c7[4] + c7[5] + c7[6];

        float cv[4] = {0.f, 0.f, 0.f, 0.f};
#pragma unroll
        for (int l = 0; l < 4; l++) {
            cv[l] = fmaf(w9[0], vg_m1[l], fmaf(w9[1], vg_m1[l + 1], fmaf(w9[2], vg_m1[l + 2], cv[l])));
            cv[l] = fmaf(w9[3], vg_0[l],  fmaf(w9[4], vg_0[l + 1],  fmaf(w9[5], vg_0[l + 2],  cv[l])));
            cv[l] = fmaf(w9[6], vg_p1[l], fmaf(w9[7], vg_p1[l + 1], fmaf(w9[8], vg_p1[l + 2], cv[l])));
        }

        float4 v4 = ld4h(V + i * W_ + j0);
        st4h(P + i * W_ + j0,
             (ax.x + ay.x) * 0.25f + v4.x + fmaf(cv[0], s, tt),
             (ax.y + ay.y) * 0.25f + v4.y + fmaf(cv[1], s, tt),
             (ax.z + ay.z) * 0.25f + v4.z + fmaf(cv[2], s, tt),
             (ax.w + ay.w) * 0.25f + v4.w + fmaf(cv[3], s, tt));

        a_m1 = a_0; a_0 = a_p1; a_p1 = a_p2;
#pragma unroll
        for (int q = 0; q < 6; q++) { vg_m1[q] = vg_0[q]; vg_0[q] = vg_p1[q]; }
    }
}

// ---------------------------------------------------------------------------
extern "C" void kernel_launch(void* const* d_in, const int* in_sizes, int n_in,
                              void* d_out, int out_size)
{
    const float* x        = (const float*)d_in[0];
    const float* qkv_w    = (const float*)d_in[1];
    const float* qkv_b    = (const float*)d_in[2];
    const float* rel_tab  = (const float*)d_in[3];
    const float* gaze_pw  = (const float*)d_in[4];
    const float* gaze_dw  = (const float*)d_in[5];
    const float* gbn_g    = (const float*)d_in[6];
    const float* gbn_b    = (const float*)d_in[7];
    const float* gbn_m    = (const float*)d_in[8];
    const float* gbn_v    = (const float*)d_in[9];
    const float* proj_w   = (const float*)d_in[10];
    const float* pbn_g    = (const float*)d_in[11];
    const float* pbn_b    = (const float*)d_in[12];
    const float* pbn_m    = (const float*)d_in[13];
    const float* pbn_v    = (const float*)d_in[14];
    float* out = (float*)d_out;

    __half *qkvh, *attnh, *vgh, *preh, *xh, *wtq, *wtg, *wtp;
    cudaGetSymbolAddress((void**)&qkvh, d_qkvh_);
    cudaGetSymbolAddress((void**)&attnh, d_attnh_);
    cudaGetSymbolAddress((void**)&vgh, d_vgh_);
    cudaGetSymbolAddress((void**)&preh, d_preh_);
    cudaGetSymbolAddress((void**)&xh, d_xh_);
    cudaGetSymbolAddress((void**)&wtq, d_wtq_);
    cudaGetSymbolAddress((void**)&wtg, d_wtg_);
    cudaGetSymbolAddress((void**)&wtp, d_wtp_);

    const int SMEM = 65536;
    cudaFuncSetAttribute(gemm_qkvA_kernel, cudaFuncAttributeMaxDynamicSharedMemorySize, QKV_SMEM);
    cudaFuncSetAttribute(gemm_h_kernel<0, true>, cudaFuncAttributeMaxDynamicSharedMemorySize, SMEM);
    cudaFuncSetAttribute(gemm_h_kernel<1, true>, cudaFuncAttributeMaxDynamicSharedMemorySize, SMEM);
    cudaFuncSetAttribute(gemm_h_kernel<2, false>, cudaFuncAttributeMaxDynamicSharedMemorySize, SMEM);
    cudaFuncSetAttribute(attn_kernel, cudaFuncAttributeMaxDynamicSharedMemorySize, SM_ATTN_TOTAL);

    // 0) weight transposes
    prepass_kernel<<<1280, 256>>>(qkv_w, gaze_pw, proj_w, wtq, wtg, wtp);

    // 1a) qkv channels 0..127 from f32 x; also emits fp16 xh
    gemm_qkvA_kernel<<<dim3(HW_ / 128, 1, B_), 256, QKV_SMEM>>>(
        wtq, x, qkvh, xh, qkv_b);

    // 1b) qkv channels 128..767 from fp16 xh (L2-resident)
    gemm_h_kernel<0, true><<<dim3(5, HW_ / 128, B_), 256, SMEM>>>(
        wtq, xh, qkvh, 768, (long long)C_ * HW_, 128,
        qkv_b, nullptr, nullptr, nullptr, nullptr);

    // 2) window attention (HMMA)
    attn_kernel<<<dim3(1024, B_), 512, SM_ATTN_TOTAL>>>(qkvh, rel_tab, attnh);

    // 3) vg(fp16) = gaze_pw @ v (in-place slice of qkv)
    gemm_h_kernel<1, true><<<dim3(2, HW_ / 128, B_), 256, SMEM>>>(
        wtg, qkvh + (long long)512 * HW_, vgh, 256, (long long)768 * HW_, 0,
        nullptr, nullptr, nullptr, nullptr, nullptr);

    // 4) pre(fp16) = (ax+ay)/4 + v + BN(dw3x3(vg))
    fuse_kernel<<<dim3(1, H_ / FROWS, B_ * C_), 64>>>(
        attnh, qkvh, vgh, gaze_dw, gbn_g, gbn_b, gbn_m, gbn_v, preh);

    // 5) out(fp32) = BN(proj_w @ pre)
    gemm_h_kernel<2, false><<<dim3(2, HW_ / 128, B_), 256, SMEM>>>(
        wtp, preh, out, 256, (long long)C_ * HW_, 0,
        nullptr, pbn_g, pbn_b, pbn_m, pbn_v);
}